// round 11
// baseline (speedup 1.0000x reference)
#include <cuda_runtime.h>
#include <cuda_bf16.h>

#define NEDGE 8192
#define DD    256
#define SPLITK 16

typedef __nv_bfloat16 bf16;
typedef unsigned int u32;

// ---------------- scratch (device globals; no allocation allowed) ----------
__device__ __align__(16) bf16 g_Xh[NEDGE * DD], g_Xl[NEDGE * DD];
__device__ __align__(16) bf16 g_eh[2][NEDGE * DD], g_el[2][NEDGE * DD];
__device__ __align__(16) bf16 g_W1h[DD * DD], g_W1l[DD * DD];
__device__ __align__(16) bf16 g_W2h[DD * DD], g_W2l[DD * DD];
__device__ __align__(16) bf16 g_W3ah[DD * DD], g_W3al[DD * DD];
__device__ __align__(16) bf16 g_Ph[2][DD * DD], g_Pl[2][DD * DD];
__device__ float g_Mpart[2][SPLITK][DD * DD];
__device__ float g_M[2][DD * DD];

// ---------------- helpers ---------------------------------------------------
__device__ __forceinline__ void cpa16(void* dst, const void* src) {
    unsigned s = (unsigned)__cvta_generic_to_shared(dst);
    asm volatile("cp.async.cg.shared.global [%0], [%1], 16;" :: "r"(s), "l"(src));
}
__device__ __forceinline__ void cpa_commit() { asm volatile("cp.async.commit_group;"); }
__device__ __forceinline__ void cpa_wait0()  { asm volatile("cp.async.wait_group 0;"); }
__device__ __forceinline__ void cpa_wait1()  { asm volatile("cp.async.wait_group 1;"); }

__device__ __forceinline__ unsigned saddr(const void* p) {
    return (unsigned)__cvta_generic_to_shared(p);
}
__device__ __forceinline__ void ldsm_x4(u32* r, unsigned a) {
    asm volatile("ldmatrix.sync.aligned.m8n8.x4.shared.b16 {%0,%1,%2,%3}, [%4];"
        : "=r"(r[0]), "=r"(r[1]), "=r"(r[2]), "=r"(r[3]) : "r"(a));
}
__device__ __forceinline__ void ldsm_x4_t(u32* r, unsigned a) {
    asm volatile("ldmatrix.sync.aligned.m8n8.x4.trans.shared.b16 {%0,%1,%2,%3}, [%4];"
        : "=r"(r[0]), "=r"(r[1]), "=r"(r[2]), "=r"(r[3]) : "r"(a));
}
__device__ __forceinline__ void mma_bf16(float* d, const u32* a, const u32* b) {
    asm volatile(
        "mma.sync.aligned.m16n8k16.row.col.f32.bf16.bf16.f32 "
        "{%0,%1,%2,%3}, {%4,%5,%6,%7}, {%8,%9}, {%0,%1,%2,%3};"
        : "+f"(d[0]), "+f"(d[1]), "+f"(d[2]), "+f"(d[3])
        : "r"(a[0]), "r"(a[1]), "r"(a[2]), "r"(a[3]), "r"(b[0]), "r"(b[1]));
}
__device__ __forceinline__ void split_store(bf16* Hp, bf16* Lp, size_t off,
                                            float v0, float v1) {
    bf16 h0 = __float2bfloat16(v0), h1 = __float2bfloat16(v1);
    bf16 l0 = __float2bfloat16(v0 - __bfloat162float(h0));
    bf16 l1 = __float2bfloat16(v1 - __bfloat162float(h1));
    __nv_bfloat162 H; H.x = h0; H.y = h1;
    __nv_bfloat162 L; L.x = l0; L.y = l1;
    *reinterpret_cast<__nv_bfloat162*>(Hp + off) = H;
    *reinterpret_cast<__nv_bfloat162*>(Lp + off) = L;
}

// ===========================================================================
// k_cvt: float4-vectorized hi/lo conversion of X and W1/W2/W3a.
// grid 2240 x 256 (exact).
// ===========================================================================
__global__ void k_cvt(const float4* __restrict__ X4, const float4* __restrict__ W14,
                      const float4* __restrict__ W24, const float4* __restrict__ W34)
{
    const int idx = blockIdx.x * 256 + threadIdx.x;
    if (idx < 524288) {
        const float4 v = X4[idx];
        const size_t o = (size_t)idx * 4;
        split_store(g_Xh, g_Xl, o,     v.x, v.y);
        split_store(g_Xh, g_Xl, o + 2, v.z, v.w);
    } else {
        const int w = idx - 524288;
        const int which = w >> 14;
        const int off4 = w & 16383;
        const float4* S = (which == 0) ? W14 : (which == 1) ? W24 : W34;
        bf16* Hd = (which == 0) ? g_W1h : (which == 1) ? g_W2h : g_W3ah;
        bf16* Ld = (which == 0) ? g_W1l : (which == 1) ? g_W2l : g_W3al;
        const float4 v = S[off4];
        const size_t o = (size_t)off4 * 4;
        split_store(Hd, Ld, o,     v.x, v.y);
        split_store(Hd, Ld, o + 2, v.z, v.w);
    }
}

// ===========================================================================
// Core: multi-pass bf16 MMA GEMM. Block tile (MI*32) x 128, 8 warps
// (2m x 4n), warp tile (MI*16) x 32, k-tile 64, 3-stage cp.async ring.
// ===========================================================================
template <int NPASS, int MI>
__device__ __forceinline__ void mma_core_rowA(
    const bf16* const* Ap, const bf16* const* Bp,
    int rowBase, int colBase, float (&acc)[MI][4][4])
{
    extern __shared__ __align__(16) char sm_raw[];
    constexpr int A_BUF = MI * 32 * 72;        // bf16 elems per stage
    bf16* sAs = (bf16*)sm_raw;
    bf16* sBs = (bf16*)(sm_raw + 3 * A_BUF * 2);

    auto as_e = [&](int b, int r, int c) -> bf16& { return sAs[b * A_BUF + r * 72 + c]; };
    auto bs_e = [&](int b, int r, int c) -> bf16& { return sBs[b * 8704 + r * 136 + c]; };

    const int tid = threadIdx.x;
    const int lane = tid & 31, w = tid >> 5;
    const int m0w = (w >> 2) * (MI * 16), n0w = (w & 3) * 32;

    auto prefetch = [&](int it, int bufn) {
        const int pass = it >> 2;
        const int k0 = (it & 3) * 64;
        const bf16* __restrict__ A = Ap[pass];
        const bf16* __restrict__ B = Bp[pass];
#pragma unroll
        for (int i = 0; i < MI; ++i) {         // A: MI*32 rows x 64 k
            const int ca = tid + 256 * i;
            const int ar = ca >> 3, ao = (ca & 7) * 8;
            cpa16(&as_e(bufn, ar, ao), A + (size_t)(rowBase + ar) * DD + k0 + ao);
        }
#pragma unroll
        for (int i = 0; i < 4; ++i) {          // B: 64 k x 128 n
            const int cb = tid + 256 * i;
            const int br = cb >> 4, bo = (cb & 15) * 8;
            cpa16(&bs_e(bufn, br, bo), B + (size_t)(k0 + br) * DD + colBase + bo);
        }
        cpa_commit();
    };

    const int t = lane >> 3;
    const int aro = (t & 1) * 8 + (lane & 7);
    const int aco = (t >> 1) * 8;
    const int bro2 = (lane & 7) + ((lane >> 3) & 1) * 8;
    const int bco2 = (lane >> 4) * 8;

    constexpr int NIT = NPASS * 4;
    prefetch(0, 0);
    prefetch(1, 1);
    for (int it = 0; it < NIT; ++it) {
        cpa_wait1();
        __syncthreads();
        if (it + 2 < NIT) prefetch(it + 2, (it + 2) % 3);
        else cpa_commit();   // keep wait-group arithmetic exact
        const int buf = it % 3;
#pragma unroll
        for (int ki = 0; ki < 4; ++ki) {
            u32 a[MI][4], bq[2][4];
#pragma unroll
            for (int mi = 0; mi < MI; ++mi)
                ldsm_x4(a[mi], saddr(&as_e(buf, m0w + mi * 16 + aro, ki * 16 + aco)));
#pragma unroll
            for (int nj = 0; nj < 2; ++nj)
                ldsm_x4_t(bq[nj], saddr(&bs_e(buf, ki * 16 + bro2, n0w + nj * 16 + bco2)));
#pragma unroll
            for (int mi = 0; mi < MI; ++mi)
#pragma unroll
                for (int ni = 0; ni < 4; ++ni)
                    mma_bf16(acc[mi][ni], a[mi], &bq[ni >> 1][(ni & 1) * 2]);
        }
    }
}

// ===========================================================================
// k_e_mma: e_z = relu(X @ W_z + b_z) -> bf16 hi/lo. MI=2, grid (2,128,2).
// ===========================================================================
__global__ void __launch_bounds__(256, 2)
k_e_mma(const float* __restrict__ b1, const float* __restrict__ b2)
{
    const int z = blockIdx.z;
    const bf16* Ap[3] = {g_Xh, g_Xh, g_Xl};
    const bf16* Bp[3] = {z ? g_W2h : g_W1h, z ? g_W2l : g_W1l, z ? g_W2h : g_W1h};
    const float* __restrict__ bias = z ? b2 : b1;
    bf16* __restrict__ Eh = g_eh[z];
    bf16* __restrict__ El = g_el[z];

    const int rowBase = blockIdx.y * 64, colBase = blockIdx.x * 128;
    float acc[2][4][4] = {};
    mma_core_rowA<3, 2>(Ap, Bp, rowBase, colBase, acc);

    const int lane = threadIdx.x & 31, w = threadIdx.x >> 5;
    const int m0w = (w >> 2) * 32, n0w = (w & 3) * 32;
    const int r_l = lane >> 2, c_l = (lane & 3) * 2;
#pragma unroll
    for (int mi = 0; mi < 2; ++mi)
#pragma unroll
        for (int ni = 0; ni < 4; ++ni) {
            const int col = colBase + n0w + ni * 8 + c_l;
            const float2 bb = *(const float2*)&bias[col];
#pragma unroll
            for (int h = 0; h < 2; ++h) {
                const int r = rowBase + m0w + mi * 16 + r_l + h * 8;
                float v0 = fmaxf(acc[mi][ni][h * 2 + 0] + bb.x, 0.f);
                float v1 = fmaxf(acc[mi][ni][h * 2 + 1] + bb.y, 0.f);
                split_store(Eh, El, (size_t)r * DD + col, v0, v1);
            }
        }
}

// ===========================================================================
// k_mpart_mma: split-K partials of M_z = e_zᵀ @ X (trans-A ldmatrix).
// grid (2, 2, 32) x 256, k-tile 64, 3-stage ring.
// ===========================================================================
#define ES_ELEM(b, r, c) sEs[(b) * 8704 + (r) * 136 + (c)]
#define XS_ELEM(b, r, c) sXs[(b) * 8704 + (r) * 136 + (c)]

__global__ void __launch_bounds__(256, 2)
k_mpart_mma()
{
    const int mat = blockIdx.z >> 4, split = blockIdx.z & 15;
    const bf16* Ap[3] = {g_eh[mat], g_eh[mat], g_el[mat]};
    const bf16* Bp[3] = {g_Xh, g_Xl, g_Xh};
    float* __restrict__ Cp = g_Mpart[mat][split];

    extern __shared__ __align__(16) char sm_raw[];
    bf16* sEs = (bf16*)sm_raw;
    bf16* sXs = (bf16*)(sm_raw + 52224);

    const int tid = threadIdx.x;
    const int lane = tid & 31, w = tid >> 5;
    const int m0w = (w >> 2) * 64, n0w = (w & 3) * 32;
    const int mBase = blockIdx.y * 128, nBase = blockIdx.x * 128;
    const int i0 = split * (NEDGE / SPLITK);

    auto prefetch = [&](int it, int bufn) {
        const int pass = it >> 3;
        const int e0 = i0 + (it & 7) * 64;
        const bf16* __restrict__ E = Ap[pass];
        const bf16* __restrict__ X = Bp[pass];
#pragma unroll
        for (int i = 0; i < 4; ++i) {
            const int c = tid + 256 * i;                // 64 rows x 128 cols
            const int r = c >> 4, o = (c & 15) * 8;
            cpa16(&ES_ELEM(bufn, r, o), E + (size_t)(e0 + r) * DD + mBase + o);
            cpa16(&XS_ELEM(bufn, r, o), X + (size_t)(e0 + r) * DD + nBase + o);
        }
        cpa_commit();
    };

    const int t = lane >> 3;
    const int akro = (t >> 1) * 8 + (lane & 7);
    const int amco = (t & 1) * 8;
    const int bro2 = (lane & 7) + ((lane >> 3) & 1) * 8;
    const int bco2 = (lane >> 4) * 8;

    float acc[4][4][4] = {};
    prefetch(0, 0);
    prefetch(1, 1);
    for (int it = 0; it < 24; ++it) {
        cpa_wait1();
        __syncthreads();
        if (it + 2 < 24) prefetch(it + 2, (it + 2) % 3);
        else cpa_commit();
        const int buf = it % 3;
#pragma unroll
        for (int ki = 0; ki < 4; ++ki) {
            u32 a[4][4], bq[2][4];
#pragma unroll
            for (int mi = 0; mi < 4; ++mi)
                ldsm_x4_t(a[mi], saddr(&ES_ELEM(buf, ki * 16 + akro, m0w + mi * 16 + amco)));
#pragma unroll
            for (int nj = 0; nj < 2; ++nj)
                ldsm_x4_t(bq[nj], saddr(&XS_ELEM(buf, ki * 16 + bro2, n0w + nj * 16 + bco2)));
#pragma unroll
            for (int mi = 0; mi < 4; ++mi)
#pragma unroll
                for (int ni = 0; ni < 4; ++ni)
                    mma_bf16(acc[mi][ni], a[mi], &bq[ni >> 1][(ni & 1) * 2]);
        }
    }

    const int r_l = lane >> 2, c_l = (lane & 3) * 2;
#pragma unroll
    for (int mi = 0; mi < 4; ++mi)
#pragma unroll
        for (int ni = 0; ni < 4; ++ni) {
            const int col = nBase + n0w + ni * 8 + c_l;
#pragma unroll
            for (int h = 0; h < 2; ++h) {
                const int r = mBase + m0w + mi * 16 + r_l + h * 8;
                float2 v = make_float2(acc[mi][ni][h * 2 + 0], acc[mi][ni][h * 2 + 1]);
                *(float2*)&Cp[(size_t)r * DD + col] = v;
            }
        }
}

// ===========================================================================
// k_mreduce: 4-way thread-split + deterministic shfl_xor tree. grid 512 x 256.
// ===========================================================================
__global__ void k_mreduce()
{
    const int gid = blockIdx.x * 256 + threadIdx.x;   // 0..131071
    const int q4 = (gid & 3) * 4;
    const int o = gid >> 2;                           // 0..32767
    const int mat = o >> 14;
    const int o4 = (o & 16383) * 4;
    float4 s = *(const float4*)&g_Mpart[mat][q4][o4];
#pragma unroll
    for (int p = 1; p < 4; p++) {
        const float4 v = *(const float4*)&g_Mpart[mat][q4 + p][o4];
        s.x += v.x; s.y += v.y; s.z += v.z; s.w += v.w;
    }
#pragma unroll
    for (int d = 1; d <= 2; d <<= 1) {
        s.x += __shfl_xor_sync(0xffffffffu, s.x, d);
        s.y += __shfl_xor_sync(0xffffffffu, s.y, d);
        s.z += __shfl_xor_sync(0xffffffffu, s.z, d);
        s.w += __shfl_xor_sync(0xffffffffu, s.w, d);
    }
    if ((gid & 3) == 0) {
        const float sc = 1.0f / DD;
        s.x *= sc; s.y *= sc; s.z *= sc; s.w *= sc;
        *(float4*)&g_M[mat][o4] = s;
    }
}

// ===========================================================================
// k_p: P_z = M_z @ W3b_z (fp32, K=256 sequential) fused with hi/lo convert.
// 32x32 out tile, grid (8, 8, 2) x 256. Writes g_Ph/g_Pl directly.
// ===========================================================================
__global__ void k_p(const float* __restrict__ W3)
{
    const int mat = blockIdx.z;
    const float* __restrict__ A = g_M[mat];
    const float* __restrict__ B = W3 + (size_t)(DD + mat * DD) * DD;

    __shared__ __align__(16) float As[32][68];
    __shared__ __align__(16) float Bs[64][36];

    const int tid = threadIdx.x;
    const int mBase = blockIdx.y * 32, nBase = blockIdx.x * 32;
    const int ty = tid >> 4, tx = tid & 15;

    float a00 = 0.f, a01 = 0.f, a10 = 0.f, a11 = 0.f;

    for (int kt = 0; kt < DD; kt += 64) {
        const int c0 = tid, c1 = tid + 256;
        cpa16(&As[c0 >> 4][(c0 & 15) * 4], &A[(size_t)(mBase + (c0 >> 4)) * DD + kt + (c0 & 15) * 4]);
        cpa16(&As[c1 >> 4][(c1 & 15) * 4], &A[(size_t)(mBase + (c1 >> 4)) * DD + kt + (c1 & 15) * 4]);
        cpa16(&Bs[c0 >> 3][(c0 & 7) * 4], &B[(size_t)(kt + (c0 >> 3)) * DD + nBase + (c0 & 7) * 4]);
        cpa16(&Bs[c1 >> 3][(c1 & 7) * 4], &B[(size_t)(kt + (c1 >> 3)) * DD + nBase + (c1 & 7) * 4]);
        cpa_commit(); cpa_wait0();
        __syncthreads();
#pragma unroll
        for (int kk = 0; kk < 64; kk++) {
            const float av0 = As[ty * 2 + 0][kk];
            const float av1 = As[ty * 2 + 1][kk];
            const float2 bv = *(const float2*)&Bs[kk][tx * 2];
            a00 = fmaf(av0, bv.x, a00); a01 = fmaf(av0, bv.y, a01);
            a10 = fmaf(av1, bv.x, a10); a11 = fmaf(av1, bv.y, a11);
        }
        __syncthreads();
    }

    split_store(g_Ph[mat], g_Pl[mat], (size_t)(mBase + ty * 2 + 0) * DD + nBase + tx * 2, a00, a01);
    split_store(g_Ph[mat], g_Pl[mat], (size_t)(mBase + ty * 2 + 1) * DD + nBase + tx * 2, a10, a11);
}

// ===========================================================================
// k_final_mma: out = relu(X@W3a + e1@P1 + e2@P2 + b3). 7 passes, MI=2
// (64-row tiles), grid (2, 128) = 256 blocks.
// ===========================================================================
__global__ void __launch_bounds__(256, 2)
k_final_mma(const float* __restrict__ b3, float* __restrict__ out)
{
    const bf16* Ap[7] = {g_Xh,
                         g_eh[0], g_eh[0], g_el[0],
                         g_eh[1], g_eh[1], g_el[1]};
    const bf16* Bp[7] = {g_W3ah,
                         g_Ph[0], g_Pl[0], g_Ph[0],
                         g_Ph[1], g_Pl[1], g_Ph[1]};

    const int rowBase = blockIdx.y * 64, colBase = blockIdx.x * 128;
    float acc[2][4][4] = {};
    mma_core_rowA<7, 2>(Ap, Bp, rowBase, colBase, acc);

    const int lane = threadIdx.x & 31, w = threadIdx.x >> 5;
    const int m0w = (w >> 2) * 32, n0w = (w & 3) * 32;
    const int r_l = lane >> 2, c_l = (lane & 3) * 2;
#pragma unroll
    for (int mi = 0; mi < 2; ++mi)
#pragma unroll
        for (int ni = 0; ni < 4; ++ni) {
            const int col = colBase + n0w + ni * 8 + c_l;
            const float2 bb = *(const float2*)&b3[col];
#pragma unroll
            for (int h = 0; h < 2; ++h) {
                const int r = rowBase + m0w + mi * 16 + r_l + h * 8;
                float2 v;
                v.x = fmaxf(acc[mi][ni][h * 2 + 0] + bb.x, 0.f);
                v.y = fmaxf(acc[mi][ni][h * 2 + 1] + bb.y, 0.f);
                *(float2*)&out[(size_t)r * DD + col] = v;
            }
        }
}

// ---------------------------------------------------------------------------
// Inputs (metadata order):
// 0 edge_pred[8192] f32 | 1 edge_corner[8192,2] i64 | 2 all_corners[4096,2] f32
// 3 edge_x[8192,256] f32 | 4 image_x[1024] f32 | 5 W1[256,256] | 6 b1[256]
// 7 W2[256,256] | 8 b2[256] | 9 W3[768,256] | 10 b3[256]
// Output: [8192, 256] f32
// ---------------------------------------------------------------------------
extern "C" void kernel_launch(void* const* d_in, const int* in_sizes, int n_in,
                              void* d_out, int out_size)
{
    (void)in_sizes; (void)n_in; (void)out_size;
    const float* X  = (const float*)d_in[3];
    const float* W1 = (const float*)d_in[5];
    const float* b1 = (const float*)d_in[6];
    const float* W2 = (const float*)d_in[7];
    const float* b2 = (const float*)d_in[8];
    const float* W3 = (const float*)d_in[9];
    const float* b3 = (const float*)d_in[10];
    float* out = (float*)d_out;

    const int SMEM_MI2   = 3 * 64 * 72 * 2 + 3 * 64 * 136 * 2;   // 79872 B
    const int SMEM_MPART = 2 * 52224;                             // 104448 B
    cudaFuncSetAttribute(k_e_mma, cudaFuncAttributeMaxDynamicSharedMemorySize, SMEM_MI2);
    cudaFuncSetAttribute(k_final_mma, cudaFuncAttributeMaxDynamicSharedMemorySize, SMEM_MI2);
    cudaFuncSetAttribute(k_mpart_mma, cudaFuncAttributeMaxDynamicSharedMemorySize, SMEM_MPART);

    k_cvt<<<2240, 256>>>((const float4*)X, (const float4*)W1,
                         (const float4*)W2, (const float4*)W3);
    k_e_mma<<<dim3(2, 128, 2), 256, SMEM_MI2>>>(b1, b2);
    k_mpart_mma<<<dim3(2, 2, 32), 256, SMEM_MPART>>>();
    k_mreduce<<<512, 256>>>();
    k_p<<<dim3(8, 8, 2), 256>>>(W3);
    k_final_mma<<<dim3(2, 128), 256, SMEM_MI2>>>(b3, out);
}

// round 12
// speedup vs baseline: 1.0420x; 1.0420x over previous
#include <cuda_runtime.h>
#include <cuda_bf16.h>

#define NEDGE 8192
#define DD    256
#define SPLITK 16

typedef __nv_bfloat16 bf16;
typedef unsigned int u32;

// ---------------- scratch (device globals; no allocation allowed) ----------
__device__ __align__(16) bf16 g_Xh[NEDGE * DD], g_Xl[NEDGE * DD];
__device__ __align__(16) bf16 g_eh[2][NEDGE * DD], g_el[2][NEDGE * DD];
__device__ __align__(16) bf16 g_W1h[DD * DD], g_W1l[DD * DD];
__device__ __align__(16) bf16 g_W2h[DD * DD], g_W2l[DD * DD];
__device__ __align__(16) bf16 g_W3ah[DD * DD], g_W3al[DD * DD];
__device__ __align__(16) bf16 g_Ph[2][DD * DD], g_Pl[2][DD * DD];
__device__ float g_Mpart[2][SPLITK][DD * DD];
__device__ float g_M[2][DD * DD];

// ---------------- helpers ---------------------------------------------------
__device__ __forceinline__ void cpa16(void* dst, const void* src) {
    unsigned s = (unsigned)__cvta_generic_to_shared(dst);
    asm volatile("cp.async.cg.shared.global [%0], [%1], 16;" :: "r"(s), "l"(src));
}
__device__ __forceinline__ void cpa_commit() { asm volatile("cp.async.commit_group;"); }
__device__ __forceinline__ void cpa_wait0()  { asm volatile("cp.async.wait_group 0;"); }
__device__ __forceinline__ void cpa_wait1()  { asm volatile("cp.async.wait_group 1;"); }

__device__ __forceinline__ unsigned saddr(const void* p) {
    return (unsigned)__cvta_generic_to_shared(p);
}
__device__ __forceinline__ void ldsm_x4(u32* r, unsigned a) {
    asm volatile("ldmatrix.sync.aligned.m8n8.x4.shared.b16 {%0,%1,%2,%3}, [%4];"
        : "=r"(r[0]), "=r"(r[1]), "=r"(r[2]), "=r"(r[3]) : "r"(a));
}
__device__ __forceinline__ void ldsm_x4_t(u32* r, unsigned a) {
    asm volatile("ldmatrix.sync.aligned.m8n8.x4.trans.shared.b16 {%0,%1,%2,%3}, [%4];"
        : "=r"(r[0]), "=r"(r[1]), "=r"(r[2]), "=r"(r[3]) : "r"(a));
}
__device__ __forceinline__ void mma_bf16(float* d, const u32* a, const u32* b) {
    asm volatile(
        "mma.sync.aligned.m16n8k16.row.col.f32.bf16.bf16.f32 "
        "{%0,%1,%2,%3}, {%4,%5,%6,%7}, {%8,%9}, {%0,%1,%2,%3};"
        : "+f"(d[0]), "+f"(d[1]), "+f"(d[2]), "+f"(d[3])
        : "r"(a[0]), "r"(a[1]), "r"(a[2]), "r"(a[3]), "r"(b[0]), "r"(b[1]));
}
__device__ __forceinline__ void split_store(bf16* Hp, bf16* Lp, size_t off,
                                            float v0, float v1) {
    bf16 h0 = __float2bfloat16(v0), h1 = __float2bfloat16(v1);
    bf16 l0 = __float2bfloat16(v0 - __bfloat162float(h0));
    bf16 l1 = __float2bfloat16(v1 - __bfloat162float(h1));
    __nv_bfloat162 H; H.x = h0; H.y = h1;
    __nv_bfloat162 L; L.x = l0; L.y = l1;
    *reinterpret_cast<__nv_bfloat162*>(Hp + off) = H;
    *reinterpret_cast<__nv_bfloat162*>(Lp + off) = L;
}

// ===========================================================================
// k_cvt: float4-vectorized hi/lo conversion of X and W1/W2/W3a.
// grid 2240 x 256 (exact).
// ===========================================================================
__global__ void k_cvt(const float4* __restrict__ X4, const float4* __restrict__ W14,
                      const float4* __restrict__ W24, const float4* __restrict__ W34)
{
    const int idx = blockIdx.x * 256 + threadIdx.x;
    if (idx < 524288) {
        const float4 v = X4[idx];
        const size_t o = (size_t)idx * 4;
        split_store(g_Xh, g_Xl, o,     v.x, v.y);
        split_store(g_Xh, g_Xl, o + 2, v.z, v.w);
    } else {
        const int w = idx - 524288;
        const int which = w >> 14;
        const int off4 = w & 16383;
        const float4* S = (which == 0) ? W14 : (which == 1) ? W24 : W34;
        bf16* Hd = (which == 0) ? g_W1h : (which == 1) ? g_W2h : g_W3ah;
        bf16* Ld = (which == 0) ? g_W1l : (which == 1) ? g_W2l : g_W3al;
        const float4 v = S[off4];
        const size_t o = (size_t)off4 * 4;
        split_store(Hd, Ld, o,     v.x, v.y);
        split_store(Hd, Ld, o + 2, v.z, v.w);
    }
}

// ===========================================================================
// Core: multi-pass bf16 MMA GEMM. Block tile (MI*32) x 128, 8 warps
// (2m x 4n), warp tile (MI*16) x 32, k-tile 64, 3-stage cp.async ring.
// ===========================================================================
template <int NPASS, int MI>
__device__ __forceinline__ void mma_core_rowA(
    const bf16* const* Ap, const bf16* const* Bp,
    int rowBase, int colBase, float (&acc)[MI][4][4])
{
    extern __shared__ __align__(16) char sm_raw[];
    constexpr int A_BUF = MI * 32 * 72;        // bf16 elems per stage
    bf16* sAs = (bf16*)sm_raw;
    bf16* sBs = (bf16*)(sm_raw + 3 * A_BUF * 2);

    auto as_e = [&](int b, int r, int c) -> bf16& { return sAs[b * A_BUF + r * 72 + c]; };
    auto bs_e = [&](int b, int r, int c) -> bf16& { return sBs[b * 8704 + r * 136 + c]; };

    const int tid = threadIdx.x;
    const int lane = tid & 31, w = tid >> 5;
    const int m0w = (w >> 2) * (MI * 16), n0w = (w & 3) * 32;

    auto prefetch = [&](int it, int bufn) {
        const int pass = it >> 2;
        const int k0 = (it & 3) * 64;
        const bf16* __restrict__ A = Ap[pass];
        const bf16* __restrict__ B = Bp[pass];
#pragma unroll
        for (int i = 0; i < MI; ++i) {         // A: MI*32 rows x 64 k
            const int ca = tid + 256 * i;
            const int ar = ca >> 3, ao = (ca & 7) * 8;
            cpa16(&as_e(bufn, ar, ao), A + (size_t)(rowBase + ar) * DD + k0 + ao);
        }
#pragma unroll
        for (int i = 0; i < 4; ++i) {          // B: 64 k x 128 n
            const int cb = tid + 256 * i;
            const int br = cb >> 4, bo = (cb & 15) * 8;
            cpa16(&bs_e(bufn, br, bo), B + (size_t)(k0 + br) * DD + colBase + bo);
        }
        cpa_commit();
    };

    const int t = lane >> 3;
    const int aro = (t & 1) * 8 + (lane & 7);
    const int aco = (t >> 1) * 8;
    const int bro2 = (lane & 7) + ((lane >> 3) & 1) * 8;
    const int bco2 = (lane >> 4) * 8;

    constexpr int NIT = NPASS * 4;
    prefetch(0, 0);
    prefetch(1, 1);
    for (int it = 0; it < NIT; ++it) {
        cpa_wait1();
        __syncthreads();
        if (it + 2 < NIT) prefetch(it + 2, (it + 2) % 3);
        else cpa_commit();   // keep wait-group arithmetic exact
        const int buf = it % 3;
#pragma unroll
        for (int ki = 0; ki < 4; ++ki) {
            u32 a[MI][4], bq[2][4];
#pragma unroll
            for (int mi = 0; mi < MI; ++mi)
                ldsm_x4(a[mi], saddr(&as_e(buf, m0w + mi * 16 + aro, ki * 16 + aco)));
#pragma unroll
            for (int nj = 0; nj < 2; ++nj)
                ldsm_x4_t(bq[nj], saddr(&bs_e(buf, ki * 16 + bro2, n0w + nj * 16 + bco2)));
#pragma unroll
            for (int mi = 0; mi < MI; ++mi)
#pragma unroll
                for (int ni = 0; ni < 4; ++ni)
                    mma_bf16(acc[mi][ni], a[mi], &bq[ni >> 1][(ni & 1) * 2]);
        }
    }
}

// ===========================================================================
// k_e_mma: e_z = relu(X @ W_z + b_z) -> bf16 hi/lo. MI=4, grid (2, 64, 2).
// ===========================================================================
__global__ void __launch_bounds__(256, 2)
k_e_mma(const float* __restrict__ b1, const float* __restrict__ b2)
{
    const int z = blockIdx.z;
    const bf16* Ap[3] = {g_Xh, g_Xh, g_Xl};
    const bf16* Bp[3] = {z ? g_W2h : g_W1h, z ? g_W2l : g_W1l, z ? g_W2h : g_W1h};
    const float* __restrict__ bias = z ? b2 : b1;
    bf16* __restrict__ Eh = g_eh[z];
    bf16* __restrict__ El = g_el[z];

    const int rowBase = blockIdx.y * 128, colBase = blockIdx.x * 128;
    float acc[4][4][4] = {};
    mma_core_rowA<3, 4>(Ap, Bp, rowBase, colBase, acc);

    const int lane = threadIdx.x & 31, w = threadIdx.x >> 5;
    const int m0w = (w >> 2) * 64, n0w = (w & 3) * 32;
    const int r_l = lane >> 2, c_l = (lane & 3) * 2;
#pragma unroll
    for (int mi = 0; mi < 4; ++mi)
#pragma unroll
        for (int ni = 0; ni < 4; ++ni) {
            const int col = colBase + n0w + ni * 8 + c_l;
            const float2 bb = *(const float2*)&bias[col];
#pragma unroll
            for (int h = 0; h < 2; ++h) {
                const int r = rowBase + m0w + mi * 16 + r_l + h * 8;
                float v0 = fmaxf(acc[mi][ni][h * 2 + 0] + bb.x, 0.f);
                float v1 = fmaxf(acc[mi][ni][h * 2 + 1] + bb.y, 0.f);
                split_store(Eh, El, (size_t)r * DD + col, v0, v1);
            }
        }
}

// ===========================================================================
// k_mpart_mma: split-K partials of M_z = e_zᵀ @ X (trans-A ldmatrix).
// grid (2, 2, 32) x 256, k-tile 64, 3-stage ring.
// ===========================================================================
#define ES_ELEM(b, r, c) sEs[(b) * 8704 + (r) * 136 + (c)]
#define XS_ELEM(b, r, c) sXs[(b) * 8704 + (r) * 136 + (c)]

__global__ void __launch_bounds__(256, 2)
k_mpart_mma()
{
    const int mat = blockIdx.z >> 4, split = blockIdx.z & 15;
    const bf16* Ap[3] = {g_eh[mat], g_eh[mat], g_el[mat]};
    const bf16* Bp[3] = {g_Xh, g_Xl, g_Xh};
    float* __restrict__ Cp = g_Mpart[mat][split];

    extern __shared__ __align__(16) char sm_raw[];
    bf16* sEs = (bf16*)sm_raw;
    bf16* sXs = (bf16*)(sm_raw + 52224);

    const int tid = threadIdx.x;
    const int lane = tid & 31, w = tid >> 5;
    const int m0w = (w >> 2) * 64, n0w = (w & 3) * 32;
    const int mBase = blockIdx.y * 128, nBase = blockIdx.x * 128;
    const int i0 = split * (NEDGE / SPLITK);

    auto prefetch = [&](int it, int bufn) {
        const int pass = it >> 3;
        const int e0 = i0 + (it & 7) * 64;
        const bf16* __restrict__ E = Ap[pass];
        const bf16* __restrict__ X = Bp[pass];
#pragma unroll
        for (int i = 0; i < 4; ++i) {
            const int c = tid + 256 * i;                // 64 rows x 128 cols
            const int r = c >> 4, o = (c & 15) * 8;
            cpa16(&ES_ELEM(bufn, r, o), E + (size_t)(e0 + r) * DD + mBase + o);
            cpa16(&XS_ELEM(bufn, r, o), X + (size_t)(e0 + r) * DD + nBase + o);
        }
        cpa_commit();
    };

    const int t = lane >> 3;
    const int akro = (t >> 1) * 8 + (lane & 7);
    const int amco = (t & 1) * 8;
    const int bro2 = (lane & 7) + ((lane >> 3) & 1) * 8;
    const int bco2 = (lane >> 4) * 8;

    float acc[4][4][4] = {};
    prefetch(0, 0);
    prefetch(1, 1);
    for (int it = 0; it < 24; ++it) {
        cpa_wait1();
        __syncthreads();
        if (it + 2 < 24) prefetch(it + 2, (it + 2) % 3);
        else cpa_commit();
        const int buf = it % 3;
#pragma unroll
        for (int ki = 0; ki < 4; ++ki) {
            u32 a[4][4], bq[2][4];
#pragma unroll
            for (int mi = 0; mi < 4; ++mi)
                ldsm_x4_t(a[mi], saddr(&ES_ELEM(buf, ki * 16 + akro, m0w + mi * 16 + amco)));
#pragma unroll
            for (int nj = 0; nj < 2; ++nj)
                ldsm_x4_t(bq[nj], saddr(&XS_ELEM(buf, ki * 16 + bro2, n0w + nj * 16 + bco2)));
#pragma unroll
            for (int mi = 0; mi < 4; ++mi)
#pragma unroll
                for (int ni = 0; ni < 4; ++ni)
                    mma_bf16(acc[mi][ni], a[mi], &bq[ni >> 1][(ni & 1) * 2]);
        }
    }

    const int r_l = lane >> 2, c_l = (lane & 3) * 2;
#pragma unroll
    for (int mi = 0; mi < 4; ++mi)
#pragma unroll
        for (int ni = 0; ni < 4; ++ni) {
            const int col = nBase + n0w + ni * 8 + c_l;
#pragma unroll
            for (int h = 0; h < 2; ++h) {
                const int r = mBase + m0w + mi * 16 + r_l + h * 8;
                float2 v = make_float2(acc[mi][ni][h * 2 + 0], acc[mi][ni][h * 2 + 1]);
                *(float2*)&Cp[(size_t)r * DD + col] = v;
            }
        }
}

// ===========================================================================
// k_mreduce: 4-way thread-split + deterministic shfl_xor tree. grid 512 x 256.
// ===========================================================================
__global__ void k_mreduce()
{
    const int gid = blockIdx.x * 256 + threadIdx.x;   // 0..131071
    const int q4 = (gid & 3) * 4;
    const int o = gid >> 2;                           // 0..32767
    const int mat = o >> 14;
    const int o4 = (o & 16383) * 4;
    float4 s = *(const float4*)&g_Mpart[mat][q4][o4];
#pragma unroll
    for (int p = 1; p < 4; p++) {
        const float4 v = *(const float4*)&g_Mpart[mat][q4 + p][o4];
        s.x += v.x; s.y += v.y; s.z += v.z; s.w += v.w;
    }
#pragma unroll
    for (int d = 1; d <= 2; d <<= 1) {
        s.x += __shfl_xor_sync(0xffffffffu, s.x, d);
        s.y += __shfl_xor_sync(0xffffffffu, s.y, d);
        s.z += __shfl_xor_sync(0xffffffffu, s.z, d);
        s.w += __shfl_xor_sync(0xffffffffu, s.w, d);
    }
    if ((gid & 3) == 0) {
        const float sc = 1.0f / DD;
        s.x *= sc; s.y *= sc; s.z *= sc; s.w *= sc;
        *(float4*)&g_M[mat][o4] = s;
    }
}

// ===========================================================================
// k_p: P_z = M_z @ W3b_z (fp32, K=256 sequential) fused with hi/lo convert.
// 32x32 out tile, grid (8, 8, 2) x 256. Writes g_Ph/g_Pl directly.
// ===========================================================================
__global__ void k_p(const float* __restrict__ W3)
{
    const int mat = blockIdx.z;
    const float* __restrict__ A = g_M[mat];
    const float* __restrict__ B = W3 + (size_t)(DD + mat * DD) * DD;

    __shared__ __align__(16) float As[32][68];
    __shared__ __align__(16) float Bs[64][36];

    const int tid = threadIdx.x;
    const int mBase = blockIdx.y * 32, nBase = blockIdx.x * 32;
    const int ty = tid >> 4, tx = tid & 15;

    float a00 = 0.f, a01 = 0.f, a10 = 0.f, a11 = 0.f;

    for (int kt = 0; kt < DD; kt += 64) {
        const int c0 = tid, c1 = tid + 256;
        cpa16(&As[c0 >> 4][(c0 & 15) * 4], &A[(size_t)(mBase + (c0 >> 4)) * DD + kt + (c0 & 15) * 4]);
        cpa16(&As[c1 >> 4][(c1 & 15) * 4], &A[(size_t)(mBase + (c1 >> 4)) * DD + kt + (c1 & 15) * 4]);
        cpa16(&Bs[c0 >> 3][(c0 & 7) * 4], &B[(size_t)(kt + (c0 >> 3)) * DD + nBase + (c0 & 7) * 4]);
        cpa16(&Bs[c1 >> 3][(c1 & 7) * 4], &B[(size_t)(kt + (c1 >> 3)) * DD + nBase + (c1 & 7) * 4]);
        cpa_commit(); cpa_wait0();
        __syncthreads();
#pragma unroll
        for (int kk = 0; kk < 64; kk++) {
            const float av0 = As[ty * 2 + 0][kk];
            const float av1 = As[ty * 2 + 1][kk];
            const float2 bv = *(const float2*)&Bs[kk][tx * 2];
            a00 = fmaf(av0, bv.x, a00); a01 = fmaf(av0, bv.y, a01);
            a10 = fmaf(av1, bv.x, a10); a11 = fmaf(av1, bv.y, a11);
        }
        __syncthreads();
    }

    split_store(g_Ph[mat], g_Pl[mat], (size_t)(mBase + ty * 2 + 0) * DD + nBase + tx * 2, a00, a01);
    split_store(g_Ph[mat], g_Pl[mat], (size_t)(mBase + ty * 2 + 1) * DD + nBase + tx * 2, a10, a11);
}

// ===========================================================================
// k_final_mma: out = relu(X@W3a + e1@P1 + e2@P2 + b3). 7 passes, MI=2
// (64-row tiles), grid (2, 128) = 256 blocks -> 2 CTAs/SM overlap.
// ===========================================================================
__global__ void __launch_bounds__(256, 2)
k_final_mma(const float* __restrict__ b3, float* __restrict__ out)
{
    const bf16* Ap[7] = {g_Xh,
                         g_eh[0], g_eh[0], g_el[0],
                         g_eh[1], g_eh[1], g_el[1]};
    const bf16* Bp[7] = {g_W3ah,
                         g_Ph[0], g_Pl[0], g_Ph[0],
                         g_Ph[1], g_Pl[1], g_Ph[1]};

    const int rowBase = blockIdx.y * 64, colBase = blockIdx.x * 128;
    float acc[2][4][4] = {};
    mma_core_rowA<7, 2>(Ap, Bp, rowBase, colBase, acc);

    const int lane = threadIdx.x & 31, w = threadIdx.x >> 5;
    const int m0w = (w >> 2) * 32, n0w = (w & 3) * 32;
    const int r_l = lane >> 2, c_l = (lane & 3) * 2;
#pragma unroll
    for (int mi = 0; mi < 2; ++mi)
#pragma unroll
        for (int ni = 0; ni < 4; ++ni) {
            const int col = colBase + n0w + ni * 8 + c_l;
            const float2 bb = *(const float2*)&b3[col];
#pragma unroll
            for (int h = 0; h < 2; ++h) {
                const int r = rowBase + m0w + mi * 16 + r_l + h * 8;
                float2 v;
                v.x = fmaxf(acc[mi][ni][h * 2 + 0] + bb.x, 0.f);
                v.y = fmaxf(acc[mi][ni][h * 2 + 1] + bb.y, 0.f);
                *(float2*)&out[(size_t)r * DD + col] = v;
            }
        }
}

// ---------------------------------------------------------------------------
// Inputs (metadata order):
// 0 edge_pred[8192] f32 | 1 edge_corner[8192,2] i64 | 2 all_corners[4096,2] f32
// 3 edge_x[8192,256] f32 | 4 image_x[1024] f32 | 5 W1[256,256] | 6 b1[256]
// 7 W2[256,256] | 8 b2[256] | 9 W3[768,256] | 10 b3[256]
// Output: [8192, 256] f32
// ---------------------------------------------------------------------------
extern "C" void kernel_launch(void* const* d_in, const int* in_sizes, int n_in,
                              void* d_out, int out_size)
{
    (void)in_sizes; (void)n_in; (void)out_size;
    const float* X  = (const float*)d_in[3];
    const float* W1 = (const float*)d_in[5];
    const float* b1 = (const float*)d_in[6];
    const float* W2 = (const float*)d_in[7];
    const float* b2 = (const float*)d_in[8];
    const float* W3 = (const float*)d_in[9];
    const float* b3 = (const float*)d_in[10];
    float* out = (float*)d_out;

    const int SMEM_E     = 3 * 128 * 72 * 2 + 3 * 64 * 136 * 2;  // 107520 B (MI=4)
    const int SMEM_FINAL = 3 * 64 * 72 * 2 + 3 * 64 * 136 * 2;   //  79872 B (MI=2)
    const int SMEM_MPART = 2 * 52224;                             // 104448 B
    cudaFuncSetAttribute(k_e_mma, cudaFuncAttributeMaxDynamicSharedMemorySize, SMEM_E);
    cudaFuncSetAttribute(k_final_mma, cudaFuncAttributeMaxDynamicSharedMemorySize, SMEM_FINAL);
    cudaFuncSetAttribute(k_mpart_mma, cudaFuncAttributeMaxDynamicSharedMemorySize, SMEM_MPART);

    k_cvt<<<2240, 256>>>((const float4*)X, (const float4*)W1,
                         (const float4*)W2, (const float4*)W3);
    k_e_mma<<<dim3(2, 64, 2), 256, SMEM_E>>>(b1, b2);
    k_mpart_mma<<<dim3(2, 2, 32), 256, SMEM_MPART>>>();
    k_mreduce<<<512, 256>>>();
    k_p<<<dim3(8, 8, 2), 256>>>(W3);
    k_final_mma<<<dim3(2, 128), 256, SMEM_FINAL>>>(b3, out);
}

// round 13
// speedup vs baseline: 1.0611x; 1.0184x over previous
#include <cuda_runtime.h>
#include <cuda_bf16.h>

#define NEDGE 8192
#define DD    256
#define SPLITK 32

typedef __nv_bfloat16 bf16;
typedef unsigned int u32;

// ---------------- scratch (device globals; no allocation allowed) ----------
__device__ __align__(16) bf16 g_Xh[NEDGE * DD], g_Xl[NEDGE * DD];
__device__ __align__(16) bf16 g_eh[2][NEDGE * DD], g_el[2][NEDGE * DD];
__device__ __align__(16) bf16 g_W1h[DD * DD], g_W1l[DD * DD];
__device__ __align__(16) bf16 g_W2h[DD * DD], g_W2l[DD * DD];
__device__ __align__(16) bf16 g_W3ah[DD * DD], g_W3al[DD * DD];
__device__ __align__(16) bf16 g_Ph[2][DD * DD], g_Pl[2][DD * DD];
__device__ float g_Mpart[2][SPLITK][DD * DD];
__device__ float g_M[2][DD * DD];

// ---------------- helpers ---------------------------------------------------
__device__ __forceinline__ void cpa16(void* dst, const void* src) {
    unsigned s = (unsigned)__cvta_generic_to_shared(dst);
    asm volatile("cp.async.cg.shared.global [%0], [%1], 16;" :: "r"(s), "l"(src));
}
__device__ __forceinline__ void cpa_commit() { asm volatile("cp.async.commit_group;"); }
__device__ __forceinline__ void cpa_wait0()  { asm volatile("cp.async.wait_group 0;"); }
__device__ __forceinline__ void cpa_wait1()  { asm volatile("cp.async.wait_group 1;"); }

__device__ __forceinline__ unsigned saddr(const void* p) {
    return (unsigned)__cvta_generic_to_shared(p);
}
__device__ __forceinline__ void ldsm_x4(u32* r, unsigned a) {
    asm volatile("ldmatrix.sync.aligned.m8n8.x4.shared.b16 {%0,%1,%2,%3}, [%4];"
        : "=r"(r[0]), "=r"(r[1]), "=r"(r[2]), "=r"(r[3]) : "r"(a));
}
__device__ __forceinline__ void ldsm_x4_t(u32* r, unsigned a) {
    asm volatile("ldmatrix.sync.aligned.m8n8.x4.trans.shared.b16 {%0,%1,%2,%3}, [%4];"
        : "=r"(r[0]), "=r"(r[1]), "=r"(r[2]), "=r"(r[3]) : "r"(a));
}
__device__ __forceinline__ void mma_bf16(float* d, const u32* a, const u32* b) {
    asm volatile(
        "mma.sync.aligned.m16n8k16.row.col.f32.bf16.bf16.f32 "
        "{%0,%1,%2,%3}, {%4,%5,%6,%7}, {%8,%9}, {%0,%1,%2,%3};"
        : "+f"(d[0]), "+f"(d[1]), "+f"(d[2]), "+f"(d[3])
        : "r"(a[0]), "r"(a[1]), "r"(a[2]), "r"(a[3]), "r"(b[0]), "r"(b[1]));
}
__device__ __forceinline__ void split_store(bf16* Hp, bf16* Lp, size_t off,
                                            float v0, float v1) {
    bf16 h0 = __float2bfloat16(v0), h1 = __float2bfloat16(v1);
    bf16 l0 = __float2bfloat16(v0 - __bfloat162float(h0));
    bf16 l1 = __float2bfloat16(v1 - __bfloat162float(h1));
    __nv_bfloat162 H; H.x = h0; H.y = h1;
    __nv_bfloat162 L; L.x = l0; L.y = l1;
    *reinterpret_cast<__nv_bfloat162*>(Hp + off) = H;
    *reinterpret_cast<__nv_bfloat162*>(Lp + off) = L;
}

// ===========================================================================
// k_cvt: float4-vectorized hi/lo conversion of X and W1/W2/W3a.
// grid 2240 x 256 (exact).
// ===========================================================================
__global__ void k_cvt(const float4* __restrict__ X4, const float4* __restrict__ W14,
                      const float4* __restrict__ W24, const float4* __restrict__ W34)
{
    const int idx = blockIdx.x * 256 + threadIdx.x;
    if (idx < 524288) {
        const float4 v = X4[idx];
        const size_t o = (size_t)idx * 4;
        split_store(g_Xh, g_Xl, o,     v.x, v.y);
        split_store(g_Xh, g_Xl, o + 2, v.z, v.w);
    } else {
        const int w = idx - 524288;
        const int which = w >> 14;
        const int off4 = w & 16383;
        const float4* S = (which == 0) ? W14 : (which == 1) ? W24 : W34;
        bf16* Hd = (which == 0) ? g_W1h : (which == 1) ? g_W2h : g_W3ah;
        bf16* Ld = (which == 0) ? g_W1l : (which == 1) ? g_W2l : g_W3al;
        const float4 v = S[off4];
        const size_t o = (size_t)off4 * 4;
        split_store(Hd, Ld, o,     v.x, v.y);
        split_store(Hd, Ld, o + 2, v.z, v.w);
    }
}

// ===========================================================================
// Core: multi-pass bf16 MMA GEMM. Block tile 128 x 128, 8 warps (2m x 4n),
// warp tile 64x32, k-tile 64, 3-stage cp.async ring.
// smem: As 3*128*72*2 (55296B) + Bs 3*64*136*2 (52224B) = 107520 B.
// ===========================================================================
#define AS_ELEM(b, r, c) sAs[(b) * 9216 + (r) * 72 + (c)]
#define BS_ELEM(b, r, c) sBs[(b) * 8704 + (r) * 136 + (c)]

template <int NPASS>
__device__ __forceinline__ void mma_core_rowA(
    const bf16* const* Ap, const bf16* const* Bp,
    int rowBase, int colBase, float (&acc)[4][4][4])
{
    extern __shared__ __align__(16) char sm_raw[];
    bf16* sAs = (bf16*)sm_raw;
    bf16* sBs = (bf16*)(sm_raw + 55296);

    const int tid = threadIdx.x;
    const int lane = tid & 31, w = tid >> 5;
    const int m0w = (w >> 2) * 64, n0w = (w & 3) * 32;

    auto prefetch = [&](int it, int bufn) {
        const int pass = it >> 2;
        const int k0 = (it & 3) * 64;
        const bf16* __restrict__ A = Ap[pass];
        const bf16* __restrict__ B = Bp[pass];
#pragma unroll
        for (int i = 0; i < 4; ++i) {
            const int ca = tid + 256 * i;               // A: 128 rows x 64 k
            const int ar = ca >> 3, ao = (ca & 7) * 8;
            cpa16(&AS_ELEM(bufn, ar, ao), A + (size_t)(rowBase + ar) * DD + k0 + ao);
            const int cb = tid + 256 * i;               // B: 64 k x 128 n
            const int br = cb >> 4, bo = (cb & 15) * 8;
            cpa16(&BS_ELEM(bufn, br, bo), B + (size_t)(k0 + br) * DD + colBase + bo);
        }
        cpa_commit();
    };

    const int t = lane >> 3;
    const int aro = (t & 1) * 8 + (lane & 7);
    const int aco = (t >> 1) * 8;
    const int bro2 = (lane & 7) + ((lane >> 3) & 1) * 8;
    const int bco2 = (lane >> 4) * 8;

    constexpr int NIT = NPASS * 4;
    prefetch(0, 0);
    prefetch(1, 1);
    for (int it = 0; it < NIT; ++it) {
        cpa_wait1();
        __syncthreads();
        if (it + 2 < NIT) prefetch(it + 2, (it + 2) % 3);
        else cpa_commit();   // keep wait-group arithmetic exact
        const int buf = it % 3;
#pragma unroll
        for (int ki = 0; ki < 4; ++ki) {
            u32 a[4][4], bq[2][4];
#pragma unroll
            for (int mi = 0; mi < 4; ++mi)
                ldsm_x4(a[mi], saddr(&AS_ELEM(buf, m0w + mi * 16 + aro, ki * 16 + aco)));
#pragma unroll
            for (int nj = 0; nj < 2; ++nj)
                ldsm_x4_t(bq[nj], saddr(&BS_ELEM(buf, ki * 16 + bro2, n0w + nj * 16 + bco2)));
#pragma unroll
            for (int mi = 0; mi < 4; ++mi)
#pragma unroll
                for (int ni = 0; ni < 4; ++ni)
                    mma_bf16(acc[mi][ni], a[mi], &bq[ni >> 1][(ni & 1) * 2]);
        }
    }
}

// ===========================================================================
// k_e_mma: e_z = relu(X @ W_z + b_z) -> bf16 hi/lo. grid (2, 64, 2) x 256.
// ===========================================================================
__global__ void __launch_bounds__(256, 2)
k_e_mma(const float* __restrict__ b1, const float* __restrict__ b2)
{
    const int z = blockIdx.z;
    const bf16* Ap[3] = {g_Xh, g_Xh, g_Xl};
    const bf16* Bp[3] = {z ? g_W2h : g_W1h, z ? g_W2l : g_W1l, z ? g_W2h : g_W1h};
    const float* __restrict__ bias = z ? b2 : b1;
    bf16* __restrict__ Eh = g_eh[z];
    bf16* __restrict__ El = g_el[z];

    const int rowBase = blockIdx.y * 128, colBase = blockIdx.x * 128;
    float acc[4][4][4] = {};
    mma_core_rowA<3>(Ap, Bp, rowBase, colBase, acc);

    const int lane = threadIdx.x & 31, w = threadIdx.x >> 5;
    const int m0w = (w >> 2) * 64, n0w = (w & 3) * 32;
    const int r_l = lane >> 2, c_l = (lane & 3) * 2;
#pragma unroll
    for (int mi = 0; mi < 4; ++mi)
#pragma unroll
        for (int ni = 0; ni < 4; ++ni) {
            const int col = colBase + n0w + ni * 8 + c_l;
            const float2 bb = *(const float2*)&bias[col];
#pragma unroll
            for (int h = 0; h < 2; ++h) {
                const int r = rowBase + m0w + mi * 16 + r_l + h * 8;
                float v0 = fmaxf(acc[mi][ni][h * 2 + 0] + bb.x, 0.f);
                float v1 = fmaxf(acc[mi][ni][h * 2 + 1] + bb.y, 0.f);
                split_store(Eh, El, (size_t)r * DD + col, v0, v1);
            }
        }
}

// ===========================================================================
// k_mpart_mma: split-K partials of M_z = e_zᵀ @ X (trans-A ldmatrix).
// SPLITK=32 -> grid (2, 2, 64) = 256 CTAs (fills all SMs at 2 CTAs/SM).
// Edge chunk 256 per split, k-tile 64, 3-stage ring. NIT = 3*4 = 12.
// ===========================================================================
#define ES_ELEM(b, r, c) sEs[(b) * 8704 + (r) * 136 + (c)]
#define XS_ELEM(b, r, c) sXs[(b) * 8704 + (r) * 136 + (c)]

__global__ void __launch_bounds__(256, 2)
k_mpart_mma()
{
    const int mat = blockIdx.z >> 5, split = blockIdx.z & 31;
    const bf16* Ap[3] = {g_eh[mat], g_eh[mat], g_el[mat]};
    const bf16* Bp[3] = {g_Xh, g_Xl, g_Xh};
    float* __restrict__ Cp = g_Mpart[mat][split];

    extern __shared__ __align__(16) char sm_raw[];
    bf16* sEs = (bf16*)sm_raw;
    bf16* sXs = (bf16*)(sm_raw + 52224);

    const int tid = threadIdx.x;
    const int lane = tid & 31, w = tid >> 5;
    const int m0w = (w >> 2) * 64, n0w = (w & 3) * 32;
    const int mBase = blockIdx.y * 128, nBase = blockIdx.x * 128;
    const int i0 = split * (NEDGE / SPLITK);   // 256-edge chunk

    auto prefetch = [&](int it, int bufn) {
        const int pass = it >> 2;
        const int e0 = i0 + (it & 3) * 64;
        const bf16* __restrict__ E = Ap[pass];
        const bf16* __restrict__ X = Bp[pass];
#pragma unroll
        for (int i = 0; i < 4; ++i) {
            const int c = tid + 256 * i;                // 64 rows x 128 cols
            const int r = c >> 4, o = (c & 15) * 8;
            cpa16(&ES_ELEM(bufn, r, o), E + (size_t)(e0 + r) * DD + mBase + o);
            cpa16(&XS_ELEM(bufn, r, o), X + (size_t)(e0 + r) * DD + nBase + o);
        }
        cpa_commit();
    };

    const int t = lane >> 3;
    const int akro = (t >> 1) * 8 + (lane & 7);
    const int amco = (t & 1) * 8;
    const int bro2 = (lane & 7) + ((lane >> 3) & 1) * 8;
    const int bco2 = (lane >> 4) * 8;

    float acc[4][4][4] = {};
    prefetch(0, 0);
    prefetch(1, 1);
    for (int it = 0; it < 12; ++it) {
        cpa_wait1();
        __syncthreads();
        if (it + 2 < 12) prefetch(it + 2, (it + 2) % 3);
        else cpa_commit();
        const int buf = it % 3;
#pragma unroll
        for (int ki = 0; ki < 4; ++ki) {
            u32 a[4][4], bq[2][4];
#pragma unroll
            for (int mi = 0; mi < 4; ++mi)
                ldsm_x4_t(a[mi], saddr(&ES_ELEM(buf, ki * 16 + akro, m0w + mi * 16 + amco)));
#pragma unroll
            for (int nj = 0; nj < 2; ++nj)
                ldsm_x4_t(bq[nj], saddr(&XS_ELEM(buf, ki * 16 + bro2, n0w + nj * 16 + bco2)));
#pragma unroll
            for (int mi = 0; mi < 4; ++mi)
#pragma unroll
                for (int ni = 0; ni < 4; ++ni)
                    mma_bf16(acc[mi][ni], a[mi], &bq[ni >> 1][(ni & 1) * 2]);
        }
    }

    const int r_l = lane >> 2, c_l = (lane & 3) * 2;
#pragma unroll
    for (int mi = 0; mi < 4; ++mi)
#pragma unroll
        for (int ni = 0; ni < 4; ++ni) {
            const int col = nBase + n0w + ni * 8 + c_l;
#pragma unroll
            for (int h = 0; h < 2; ++h) {
                const int r = mBase + m0w + mi * 16 + r_l + h * 8;
                float2 v = make_float2(acc[mi][ni][h * 2 + 0], acc[mi][ni][h * 2 + 1]);
                *(float2*)&Cp[(size_t)r * DD + col] = v;
            }
        }
}

// ===========================================================================
// k_mreduce: 4-thread split over 32 partials (8 each) + shfl_xor tree.
// grid 512 x 256.
// ===========================================================================
__global__ void k_mreduce()
{
    const int gid = blockIdx.x * 256 + threadIdx.x;   // 0..131071
    const int q8 = (gid & 3) * 8;
    const int o = gid >> 2;                           // 0..32767
    const int mat = o >> 14;
    const int o4 = (o & 16383) * 4;
    float4 s = *(const float4*)&g_Mpart[mat][q8][o4];
#pragma unroll
    for (int p = 1; p < 8; p++) {
        const float4 v = *(const float4*)&g_Mpart[mat][q8 + p][o4];
        s.x += v.x; s.y += v.y; s.z += v.z; s.w += v.w;
    }
#pragma unroll
    for (int d = 1; d <= 2; d <<= 1) {
        s.x += __shfl_xor_sync(0xffffffffu, s.x, d);
        s.y += __shfl_xor_sync(0xffffffffu, s.y, d);
        s.z += __shfl_xor_sync(0xffffffffu, s.z, d);
        s.w += __shfl_xor_sync(0xffffffffu, s.w, d);
    }
    if ((gid & 3) == 0) {
        const float sc = 1.0f / DD;
        s.x *= sc; s.y *= sc; s.z *= sc; s.w *= sc;
        *(float4*)&g_M[mat][o4] = s;
    }
}

// ===========================================================================
// k_p: P_z = M_z @ W3b_z (fp32, K=256 sequential) fused with hi/lo convert.
// 32x32 out tile, grid (8, 8, 2) x 256. Writes g_Ph/g_Pl directly.
// ===========================================================================
__global__ void k_p(const float* __restrict__ W3)
{
    const int mat = blockIdx.z;
    const float* __restrict__ A = g_M[mat];
    const float* __restrict__ B = W3 + (size_t)(DD + mat * DD) * DD;

    __shared__ __align__(16) float As[32][68];
    __shared__ __align__(16) float Bs[64][36];

    const int tid = threadIdx.x;
    const int mBase = blockIdx.y * 32, nBase = blockIdx.x * 32;
    const int ty = tid >> 4, tx = tid & 15;

    float a00 = 0.f, a01 = 0.f, a10 = 0.f, a11 = 0.f;

    for (int kt = 0; kt < DD; kt += 64) {
        const int c0 = tid, c1 = tid + 256;
        cpa16(&As[c0 >> 4][(c0 & 15) * 4], &A[(size_t)(mBase + (c0 >> 4)) * DD + kt + (c0 & 15) * 4]);
        cpa16(&As[c1 >> 4][(c1 & 15) * 4], &A[(size_t)(mBase + (c1 >> 4)) * DD + kt + (c1 & 15) * 4]);
        cpa16(&Bs[c0 >> 3][(c0 & 7) * 4], &B[(size_t)(kt + (c0 >> 3)) * DD + nBase + (c0 & 7) * 4]);
        cpa16(&Bs[c1 >> 3][(c1 & 7) * 4], &B[(size_t)(kt + (c1 >> 3)) * DD + nBase + (c1 & 7) * 4]);
        cpa_commit(); cpa_wait0();
        __syncthreads();
#pragma unroll
        for (int kk = 0; kk < 64; kk++) {
            const float av0 = As[ty * 2 + 0][kk];
            const float av1 = As[ty * 2 + 1][kk];
            const float2 bv = *(const float2*)&Bs[kk][tx * 2];
            a00 = fmaf(av0, bv.x, a00); a01 = fmaf(av0, bv.y, a01);
            a10 = fmaf(av1, bv.x, a10); a11 = fmaf(av1, bv.y, a11);
        }
        __syncthreads();
    }

    split_store(g_Ph[mat], g_Pl[mat], (size_t)(mBase + ty * 2 + 0) * DD + nBase + tx * 2, a00, a01);
    split_store(g_Ph[mat], g_Pl[mat], (size_t)(mBase + ty * 2 + 1) * DD + nBase + tx * 2, a10, a11);
}

// ===========================================================================
// k_final_mma: out = relu(X@W3a + e1@P1 + e2@P2 + b3). 7 passes:
// X@W3a hi-only (~5% of output magnitude; corrections below error budget),
// e@P full 3-term. grid (2, 64) x 256.
// ===========================================================================
__global__ void __launch_bounds__(256, 2)
k_final_mma(const float* __restrict__ b3, float* __restrict__ out)
{
    const bf16* Ap[7] = {g_Xh,
                         g_eh[0], g_eh[0], g_el[0],
                         g_eh[1], g_eh[1], g_el[1]};
    const bf16* Bp[7] = {g_W3ah,
                         g_Ph[0], g_Pl[0], g_Ph[0],
                         g_Ph[1], g_Pl[1], g_Ph[1]};

    const int rowBase = blockIdx.y * 128, colBase = blockIdx.x * 128;
    float acc[4][4][4] = {};
    mma_core_rowA<7>(Ap, Bp, rowBase, colBase, acc);

    const int lane = threadIdx.x & 31, w = threadIdx.x >> 5;
    const int m0w = (w >> 2) * 64, n0w = (w & 3) * 32;
    const int r_l = lane >> 2, c_l = (lane & 3) * 2;
#pragma unroll
    for (int mi = 0; mi < 4; ++mi)
#pragma unroll
        for (int ni = 0; ni < 4; ++ni) {
            const int col = colBase + n0w + ni * 8 + c_l;
            const float2 bb = *(const float2*)&b3[col];
#pragma unroll
            for (int h = 0; h < 2; ++h) {
                const int r = rowBase + m0w + mi * 16 + r_l + h * 8;
                float2 v;
                v.x = fmaxf(acc[mi][ni][h * 2 + 0] + bb.x, 0.f);
                v.y = fmaxf(acc[mi][ni][h * 2 + 1] + bb.y, 0.f);
                *(float2*)&out[(size_t)r * DD + col] = v;
            }
        }
}

// ---------------------------------------------------------------------------
// Inputs (metadata order):
// 0 edge_pred[8192] f32 | 1 edge_corner[8192,2] i64 | 2 all_corners[4096,2] f32
// 3 edge_x[8192,256] f32 | 4 image_x[1024] f32 | 5 W1[256,256] | 6 b1[256]
// 7 W2[256,256] | 8 b2[256] | 9 W3[768,256] | 10 b3[256]
// Output: [8192, 256] f32
// ---------------------------------------------------------------------------
extern "C" void kernel_launch(void* const* d_in, const int* in_sizes, int n_in,
                              void* d_out, int out_size)
{
    (void)in_sizes; (void)n_in; (void)out_size;
    const float* X  = (const float*)d_in[3];
    const float* W1 = (const float*)d_in[5];
    const float* b1 = (const float*)d_in[6];
    const float* W2 = (const float*)d_in[7];
    const float* b2 = (const float*)d_in[8];
    const float* W3 = (const float*)d_in[9];
    const float* b3 = (const float*)d_in[10];
    float* out = (float*)d_out;

    const int SMEM_CORE  = 55296 + 52224;  // 107520 B
    const int SMEM_MPART = 2 * 52224;      // 104448 B
    cudaFuncSetAttribute(k_e_mma, cudaFuncAttributeMaxDynamicSharedMemorySize, SMEM_CORE);
    cudaFuncSetAttribute(k_final_mma, cudaFuncAttributeMaxDynamicSharedMemorySize, SMEM_CORE);
    cudaFuncSetAttribute(k_mpart_mma, cudaFuncAttributeMaxDynamicSharedMemorySize, SMEM_MPART);

    k_cvt<<<2240, 256>>>((const float4*)X, (const float4*)W1,
                         (const float4*)W2, (const float4*)W3);
    k_e_mma<<<dim3(2, 64, 2), 256, SMEM_CORE>>>(b1, b2);
    k_mpart_mma<<<dim3(2, 2, 64), 256, SMEM_MPART>>>();
    k_mreduce<<<512, 256>>>();
    k_p<<<dim3(8, 8, 2), 256>>>(W3);
    k_final_mma<<<dim3(2, 64), 256, SMEM_CORE>>>(b3, out);
}

// round 14
// speedup vs baseline: 1.2461x; 1.1743x over previous
#include <cuda_runtime.h>
#include <cuda_bf16.h>
#include <cuda_fp16.h>

#define NEDGE 8192
#define DD    256
#define SPLITK 32

typedef __nv_bfloat16 bf16;
typedef unsigned int u32;

// ---------------- scratch (device globals; no allocation allowed) ----------
__device__ __align__(16) bf16 g_Xh[NEDGE * DD], g_Xl[NEDGE * DD];   // X for k_e (bf16 3-term)
__device__ __align__(16) half g_X16[NEDGE * DD];                    // X fp16 (k_mpart B, k_final)
__device__ __align__(16) half g_e16h[2][NEDGE * DD], g_e16l[2][NEDGE * DD];  // e fp16 2-term
__device__ __align__(16) bf16 g_W1h[DD * DD], g_W1l[DD * DD];
__device__ __align__(16) bf16 g_W2h[DD * DD], g_W2l[DD * DD];
__device__ __align__(16) half g_W3a16[DD * DD];
__device__ __align__(16) half g_P16[2][DD * DD];
__device__ float g_Mpart[2][SPLITK][DD * DD];
__device__ float g_M[2][DD * DD];

// ---------------- helpers ---------------------------------------------------
__device__ __forceinline__ void cpa16(void* dst, const void* src) {
    unsigned s = (unsigned)__cvta_generic_to_shared(dst);
    asm volatile("cp.async.cg.shared.global [%0], [%1], 16;" :: "r"(s), "l"(src));
}
__device__ __forceinline__ void cpa_commit() { asm volatile("cp.async.commit_group;"); }
__device__ __forceinline__ void cpa_wait0()  { asm volatile("cp.async.wait_group 0;"); }
__device__ __forceinline__ void cpa_wait1()  { asm volatile("cp.async.wait_group 1;"); }

__device__ __forceinline__ unsigned saddr(const void* p) {
    return (unsigned)__cvta_generic_to_shared(p);
}
__device__ __forceinline__ void ldsm_x4(u32* r, unsigned a) {
    asm volatile("ldmatrix.sync.aligned.m8n8.x4.shared.b16 {%0,%1,%2,%3}, [%4];"
        : "=r"(r[0]), "=r"(r[1]), "=r"(r[2]), "=r"(r[3]) : "r"(a));
}
__device__ __forceinline__ void ldsm_x4_t(u32* r, unsigned a) {
    asm volatile("ldmatrix.sync.aligned.m8n8.x4.trans.shared.b16 {%0,%1,%2,%3}, [%4];"
        : "=r"(r[0]), "=r"(r[1]), "=r"(r[2]), "=r"(r[3]) : "r"(a));
}
__device__ __forceinline__ void mma_bf16(float* d, const u32* a, const u32* b) {
    asm volatile(
        "mma.sync.aligned.m16n8k16.row.col.f32.bf16.bf16.f32 "
        "{%0,%1,%2,%3}, {%4,%5,%6,%7}, {%8,%9}, {%0,%1,%2,%3};"
        : "+f"(d[0]), "+f"(d[1]), "+f"(d[2]), "+f"(d[3])
        : "r"(a[0]), "r"(a[1]), "r"(a[2]), "r"(a[3]), "r"(b[0]), "r"(b[1]));
}
__device__ __forceinline__ void mma_f16(float* d, const u32* a, const u32* b) {
    asm volatile(
        "mma.sync.aligned.m16n8k16.row.col.f32.f16.f16.f32 "
        "{%0,%1,%2,%3}, {%4,%5,%6,%7}, {%8,%9}, {%0,%1,%2,%3};"
        : "+f"(d[0]), "+f"(d[1]), "+f"(d[2]), "+f"(d[3])
        : "r"(a[0]), "r"(a[1]), "r"(a[2]), "r"(a[3]), "r"(b[0]), "r"(b[1]));
}
__device__ __forceinline__ void split_store_bf(bf16* Hp, bf16* Lp, size_t off,
                                               float v0, float v1) {
    bf16 h0 = __float2bfloat16(v0), h1 = __float2bfloat16(v1);
    bf16 l0 = __float2bfloat16(v0 - __bfloat162float(h0));
    bf16 l1 = __float2bfloat16(v1 - __bfloat162float(h1));
    __nv_bfloat162 H; H.x = h0; H.y = h1;
    __nv_bfloat162 L; L.x = l0; L.y = l1;
    *reinterpret_cast<__nv_bfloat162*>(Hp + off) = H;
    *reinterpret_cast<__nv_bfloat162*>(Lp + off) = L;
}
__device__ __forceinline__ void split_store_h(half* Hp, half* Lp, size_t off,
                                              float v0, float v1) {
    half h0 = __float2half_rn(v0), h1 = __float2half_rn(v1);
    half l0 = __float2half_rn(v0 - __half2float(h0));
    half l1 = __float2half_rn(v1 - __half2float(h1));
    half2 H; H.x = h0; H.y = h1;
    half2 L; L.x = l0; L.y = l1;
    *reinterpret_cast<half2*>(Hp + off) = H;
    *reinterpret_cast<half2*>(Lp + off) = L;
}

// ===========================================================================
// k_cvt: X -> bf16 hi/lo + fp16; W1,W2 -> bf16 hi/lo; W3a -> fp16.
// grid 2240 x 256 (exact).
// ===========================================================================
__global__ void k_cvt(const float4* __restrict__ X4, const float4* __restrict__ W14,
                      const float4* __restrict__ W24, const float4* __restrict__ W34)
{
    const int idx = blockIdx.x * 256 + threadIdx.x;
    if (idx < 524288) {
        const float4 v = X4[idx];
        const size_t o = (size_t)idx * 4;
        split_store_bf(g_Xh, g_Xl, o,     v.x, v.y);
        split_store_bf(g_Xh, g_Xl, o + 2, v.z, v.w);
        half2 a; a.x = __float2half_rn(v.x); a.y = __float2half_rn(v.y);
        half2 b; b.x = __float2half_rn(v.z); b.y = __float2half_rn(v.w);
        *reinterpret_cast<half2*>(g_X16 + o)     = a;
        *reinterpret_cast<half2*>(g_X16 + o + 2) = b;
    } else {
        const int w = idx - 524288;
        const int which = w >> 14;
        const int off4 = w & 16383;
        const size_t o = (size_t)off4 * 4;
        if (which < 2) {
            const float4 v = (which == 0) ? W14[off4] : W24[off4];
            bf16* Hd = (which == 0) ? g_W1h : g_W2h;
            bf16* Ld = (which == 0) ? g_W1l : g_W2l;
            split_store_bf(Hd, Ld, o,     v.x, v.y);
            split_store_bf(Hd, Ld, o + 2, v.z, v.w);
        } else {
            const float4 v = W34[off4];
            half2 a; a.x = __float2half_rn(v.x); a.y = __float2half_rn(v.y);
            half2 b; b.x = __float2half_rn(v.z); b.y = __float2half_rn(v.w);
            *reinterpret_cast<half2*>(g_W3a16 + o)     = a;
            *reinterpret_cast<half2*>(g_W3a16 + o + 2) = b;
        }
    }
}

// ===========================================================================
// Core: multi-pass 16-bit MMA GEMM (bf16 or fp16 via F16 flag).
// Block tile 128x128, 8 warps (2m x 4n), warp tile 64x32, k-tile 64,
// 3-stage cp.async ring. smem 107520 B.
// ===========================================================================
#define AS_ELEM(b, r, c) sAs[(b) * 9216 + (r) * 72 + (c)]
#define BS_ELEM(b, r, c) sBs[(b) * 8704 + (r) * 136 + (c)]

template <int NPASS, bool F16>
__device__ __forceinline__ void mma_core_rowA(
    const bf16* const* Ap, const bf16* const* Bp,
    int rowBase, int colBase, float (&acc)[4][4][4])
{
    extern __shared__ __align__(16) char sm_raw[];
    bf16* sAs = (bf16*)sm_raw;
    bf16* sBs = (bf16*)(sm_raw + 55296);

    const int tid = threadIdx.x;
    const int lane = tid & 31, w = tid >> 5;
    const int m0w = (w >> 2) * 64, n0w = (w & 3) * 32;

    auto prefetch = [&](int it, int bufn) {
        const int pass = it >> 2;
        const int k0 = (it & 3) * 64;
        const bf16* __restrict__ A = Ap[pass];
        const bf16* __restrict__ B = Bp[pass];
#pragma unroll
        for (int i = 0; i < 4; ++i) {
            const int ca = tid + 256 * i;               // A: 128 rows x 64 k
            const int ar = ca >> 3, ao = (ca & 7) * 8;
            cpa16(&AS_ELEM(bufn, ar, ao), A + (size_t)(rowBase + ar) * DD + k0 + ao);
            const int cb = tid + 256 * i;               // B: 64 k x 128 n
            const int br = cb >> 4, bo = (cb & 15) * 8;
            cpa16(&BS_ELEM(bufn, br, bo), B + (size_t)(k0 + br) * DD + colBase + bo);
        }
        cpa_commit();
    };

    const int t = lane >> 3;
    const int aro = (t & 1) * 8 + (lane & 7);
    const int aco = (t >> 1) * 8;
    const int bro2 = (lane & 7) + ((lane >> 3) & 1) * 8;
    const int bco2 = (lane >> 4) * 8;

    constexpr int NIT = NPASS * 4;
    prefetch(0, 0);
    prefetch(1, 1);
    for (int it = 0; it < NIT; ++it) {
        cpa_wait1();
        __syncthreads();
        if (it + 2 < NIT) prefetch(it + 2, (it + 2) % 3);
        else cpa_commit();   // keep wait-group arithmetic exact
        const int buf = it % 3;
#pragma unroll
        for (int ki = 0; ki < 4; ++ki) {
            u32 a[4][4], bq[2][4];
#pragma unroll
            for (int mi = 0; mi < 4; ++mi)
                ldsm_x4(a[mi], saddr(&AS_ELEM(buf, m0w + mi * 16 + aro, ki * 16 + aco)));
#pragma unroll
            for (int nj = 0; nj < 2; ++nj)
                ldsm_x4_t(bq[nj], saddr(&BS_ELEM(buf, ki * 16 + bro2, n0w + nj * 16 + bco2)));
#pragma unroll
            for (int mi = 0; mi < 4; ++mi)
#pragma unroll
                for (int ni = 0; ni < 4; ++ni) {
                    if (F16) mma_f16(acc[mi][ni], a[mi], &bq[ni >> 1][(ni & 1) * 2]);
                    else     mma_bf16(acc[mi][ni], a[mi], &bq[ni >> 1][(ni & 1) * 2]);
                }
        }
    }
}

// ===========================================================================
// k_e_mma: e_z = relu(X @ W_z + b_z), bf16 3-term -> fp16 hi/lo output.
// grid (2, 64, 2) x 256.
// ===========================================================================
__global__ void __launch_bounds__(256, 2)
k_e_mma(const float* __restrict__ b1, const float* __restrict__ b2)
{
    const int z = blockIdx.z;
    const bf16* Ap[3] = {g_Xh, g_Xh, g_Xl};
    const bf16* Bp[3] = {z ? g_W2h : g_W1h, z ? g_W2l : g_W1l, z ? g_W2h : g_W1h};
    const float* __restrict__ bias = z ? b2 : b1;
    half* __restrict__ Eh = g_e16h[z];
    half* __restrict__ El = g_e16l[z];

    const int rowBase = blockIdx.y * 128, colBase = blockIdx.x * 128;
    float acc[4][4][4] = {};
    mma_core_rowA<3, false>(Ap, Bp, rowBase, colBase, acc);

    const int lane = threadIdx.x & 31, w = threadIdx.x >> 5;
    const int m0w = (w >> 2) * 64, n0w = (w & 3) * 32;
    const int r_l = lane >> 2, c_l = (lane & 3) * 2;
#pragma unroll
    for (int mi = 0; mi < 4; ++mi)
#pragma unroll
        for (int ni = 0; ni < 4; ++ni) {
            const int col = colBase + n0w + ni * 8 + c_l;
            const float2 bb = *(const float2*)&bias[col];
#pragma unroll
            for (int h = 0; h < 2; ++h) {
                const int r = rowBase + m0w + mi * 16 + r_l + h * 8;
                float v0 = fmaxf(acc[mi][ni][h * 2 + 0] + bb.x, 0.f);
                float v1 = fmaxf(acc[mi][ni][h * 2 + 1] + bb.y, 0.f);
                split_store_h(Eh, El, (size_t)r * DD + col, v0, v1);
            }
        }
}

// ===========================================================================
// k_mpart_mma: split-K partials of M_z = e_zᵀ @ X. FP16 2-pass:
// (e16h + e16l)ᵀ · X16. grid (2, 2, 64) x 256, k-tile 64. NIT = 2*4 = 8.
// ===========================================================================
#define ES_ELEM(b, r, c) sEs[(b) * 8704 + (r) * 136 + (c)]
#define XS_ELEM(b, r, c) sXs[(b) * 8704 + (r) * 136 + (c)]

__global__ void __launch_bounds__(256, 2)
k_mpart_mma()
{
    const int mat = blockIdx.z >> 5, split = blockIdx.z & 31;
    const half* Ap[2] = {g_e16h[mat], g_e16l[mat]};
    float* __restrict__ Cp = g_Mpart[mat][split];

    extern __shared__ __align__(16) char sm_raw[];
    half* sEs = (half*)sm_raw;
    half* sXs = (half*)(sm_raw + 52224);

    const int tid = threadIdx.x;
    const int lane = tid & 31, w = tid >> 5;
    const int m0w = (w >> 2) * 64, n0w = (w & 3) * 32;
    const int mBase = blockIdx.y * 128, nBase = blockIdx.x * 128;
    const int i0 = split * (NEDGE / SPLITK);   // 256-edge chunk

    auto prefetch = [&](int it, int bufn) {
        const int pass = it >> 2;
        const int e0 = i0 + (it & 3) * 64;
        const half* __restrict__ E = Ap[pass];
#pragma unroll
        for (int i = 0; i < 4; ++i) {
            const int c = tid + 256 * i;                // 64 rows x 128 cols
            const int r = c >> 4, o = (c & 15) * 8;
            cpa16(&ES_ELEM(bufn, r, o), E + (size_t)(e0 + r) * DD + mBase + o);
            cpa16(&XS_ELEM(bufn, r, o), g_X16 + (size_t)(e0 + r) * DD + nBase + o);
        }
        cpa_commit();
    };

    const int t = lane >> 3;
    const int akro = (t >> 1) * 8 + (lane & 7);
    const int amco = (t & 1) * 8;
    const int bro2 = (lane & 7) + ((lane >> 3) & 1) * 8;
    const int bco2 = (lane >> 4) * 8;

    float acc[4][4][4] = {};
    prefetch(0, 0);
    prefetch(1, 1);
    for (int it = 0; it < 8; ++it) {
        cpa_wait1();
        __syncthreads();
        if (it + 2 < 8) prefetch(it + 2, (it + 2) % 3);
        else cpa_commit();
        const int buf = it % 3;
#pragma unroll
        for (int ki = 0; ki < 4; ++ki) {
            u32 a[4][4], bq[2][4];
#pragma unroll
            for (int mi = 0; mi < 4; ++mi)
                ldsm_x4_t(a[mi], saddr(&ES_ELEM(buf, ki * 16 + akro, m0w + mi * 16 + amco)));
#pragma unroll
            for (int nj = 0; nj < 2; ++nj)
                ldsm_x4_t(bq[nj], saddr(&XS_ELEM(buf, ki * 16 + bro2, n0w + nj * 16 + bco2)));
#pragma unroll
            for (int mi = 0; mi < 4; ++mi)
#pragma unroll
                for (int ni = 0; ni < 4; ++ni)
                    mma_f16(acc[mi][ni], a[mi], &bq[ni >> 1][(ni & 1) * 2]);
        }
    }

    const int r_l = lane >> 2, c_l = (lane & 3) * 2;
#pragma unroll
    for (int mi = 0; mi < 4; ++mi)
#pragma unroll
        for (int ni = 0; ni < 4; ++ni) {
            const int col = nBase + n0w + ni * 8 + c_l;
#pragma unroll
            for (int h = 0; h < 2; ++h) {
                const int r = mBase + m0w + mi * 16 + r_l + h * 8;
                float2 v = make_float2(acc[mi][ni][h * 2 + 0], acc[mi][ni][h * 2 + 1]);
                *(float2*)&Cp[(size_t)r * DD + col] = v;
            }
        }
}

// ===========================================================================
// k_mreduce: 4-thread split over 32 partials (8 each) + shfl_xor tree.
// grid 512 x 256.
// ===========================================================================
__global__ void k_mreduce()
{
    const int gid = blockIdx.x * 256 + threadIdx.x;   // 0..131071
    const int q8 = (gid & 3) * 8;
    const int o = gid >> 2;                           // 0..32767
    const int mat = o >> 14;
    const int o4 = (o & 16383) * 4;
    float4 s = *(const float4*)&g_Mpart[mat][q8][o4];
#pragma unroll
    for (int p = 1; p < 8; p++) {
        const float4 v = *(const float4*)&g_Mpart[mat][q8 + p][o4];
        s.x += v.x; s.y += v.y; s.z += v.z; s.w += v.w;
    }
#pragma unroll
    for (int d = 1; d <= 2; d <<= 1) {
        s.x += __shfl_xor_sync(0xffffffffu, s.x, d);
        s.y += __shfl_xor_sync(0xffffffffu, s.y, d);
        s.z += __shfl_xor_sync(0xffffffffu, s.z, d);
        s.w += __shfl_xor_sync(0xffffffffu, s.w, d);
    }
    if ((gid & 3) == 0) {
        const float sc = 1.0f / DD;
        s.x *= sc; s.y *= sc; s.z *= sc; s.w *= sc;
        *(float4*)&g_M[mat][o4] = s;
    }
}

// ===========================================================================
// k_p: P_z = M_z @ W3b_z (fp32, K=256 sequential), emits fp16 P.
// 32x32 out tile, grid (8, 8, 2) x 256.
// ===========================================================================
__global__ void k_p(const float* __restrict__ W3)
{
    const int mat = blockIdx.z;
    const float* __restrict__ A = g_M[mat];
    const float* __restrict__ B = W3 + (size_t)(DD + mat * DD) * DD;

    __shared__ __align__(16) float As[32][68];
    __shared__ __align__(16) float Bs[64][36];

    const int tid = threadIdx.x;
    const int mBase = blockIdx.y * 32, nBase = blockIdx.x * 32;
    const int ty = tid >> 4, tx = tid & 15;

    float a00 = 0.f, a01 = 0.f, a10 = 0.f, a11 = 0.f;

    for (int kt = 0; kt < DD; kt += 64) {
        const int c0 = tid, c1 = tid + 256;
        cpa16(&As[c0 >> 4][(c0 & 15) * 4], &A[(size_t)(mBase + (c0 >> 4)) * DD + kt + (c0 & 15) * 4]);
        cpa16(&As[c1 >> 4][(c1 & 15) * 4], &A[(size_t)(mBase + (c1 >> 4)) * DD + kt + (c1 & 15) * 4]);
        cpa16(&Bs[c0 >> 3][(c0 & 7) * 4], &B[(size_t)(kt + (c0 >> 3)) * DD + nBase + (c0 & 7) * 4]);
        cpa16(&Bs[c1 >> 3][(c1 & 7) * 4], &B[(size_t)(kt + (c1 >> 3)) * DD + nBase + (c1 & 7) * 4]);
        cpa_commit(); cpa_wait0();
        __syncthreads();
#pragma unroll
        for (int kk = 0; kk < 64; kk++) {
            const float av0 = As[ty * 2 + 0][kk];
            const float av1 = As[ty * 2 + 1][kk];
            const float2 bv = *(const float2*)&Bs[kk][tx * 2];
            a00 = fmaf(av0, bv.x, a00); a01 = fmaf(av0, bv.y, a01);
            a10 = fmaf(av1, bv.x, a10); a11 = fmaf(av1, bv.y, a11);
        }
        __syncthreads();
    }

    half2 r0; r0.x = __float2half_rn(a00); r0.y = __float2half_rn(a01);
    half2 r1; r1.x = __float2half_rn(a10); r1.y = __float2half_rn(a11);
    *reinterpret_cast<half2*>(&g_P16[mat][(size_t)(mBase + ty * 2 + 0) * DD + nBase + tx * 2]) = r0;
    *reinterpret_cast<half2*>(&g_P16[mat][(size_t)(mBase + ty * 2 + 1) * DD + nBase + tx * 2]) = r1;
}

// ===========================================================================
// k_final_mma: out = relu(X@W3a + e1@P1 + e2@P2 + b3). FP16 5-pass:
// X16·W3a16 + (e16h+e16l)·P16 per mat. grid (2, 64) x 256.
// ===========================================================================
__global__ void __launch_bounds__(256, 2)
k_final_mma(const float* __restrict__ b3, float* __restrict__ out)
{
    const bf16* Ap[5] = {(const bf16*)g_X16,
                         (const bf16*)g_e16h[0], (const bf16*)g_e16l[0],
                         (const bf16*)g_e16h[1], (const bf16*)g_e16l[1]};
    const bf16* Bp[5] = {(const bf16*)g_W3a16,
                         (const bf16*)g_P16[0], (const bf16*)g_P16[0],
                         (const bf16*)g_P16[1], (const bf16*)g_P16[1]};

    const int rowBase = blockIdx.y * 128, colBase = blockIdx.x * 128;
    float acc[4][4][4] = {};
    mma_core_rowA<5, true>(Ap, Bp, rowBase, colBase, acc);

    const int lane = threadIdx.x & 31, w = threadIdx.x >> 5;
    const int m0w = (w >> 2) * 64, n0w = (w & 3) * 32;
    const int r_l = lane >> 2, c_l = (lane & 3) * 2;
#pragma unroll
    for (int mi = 0; mi < 4; ++mi)
#pragma unroll
        for (int ni = 0; ni < 4; ++ni) {
            const int col = colBase + n0w + ni * 8 + c_l;
            const float2 bb = *(const float2*)&b3[col];
#pragma unroll
            for (int h = 0; h < 2; ++h) {
                const int r = rowBase + m0w + mi * 16 + r_l + h * 8;
                float2 v;
                v.x = fmaxf(acc[mi][ni][h * 2 + 0] + bb.x, 0.f);
                v.y = fmaxf(acc[mi][ni][h * 2 + 1] + bb.y, 0.f);
                *(float2*)&out[(size_t)r * DD + col] = v;
            }
        }
}

// ---------------------------------------------------------------------------
// Inputs (metadata order):
// 0 edge_pred[8192] f32 | 1 edge_corner[8192,2] i64 | 2 all_corners[4096,2] f32
// 3 edge_x[8192,256] f32 | 4 image_x[1024] f32 | 5 W1[256,256] | 6 b1[256]
// 7 W2[256,256] | 8 b2[256] | 9 W3[768,256] | 10 b3[256]
// Output: [8192, 256] f32
// ---------------------------------------------------------------------------
extern "C" void kernel_launch(void* const* d_in, const int* in_sizes, int n_in,
                              void* d_out, int out_size)
{
    (void)in_sizes; (void)n_in; (void)out_size;
    const float* X  = (const float*)d_in[3];
    const float* W1 = (const float*)d_in[5];
    const float* b1 = (const float*)d_in[6];
    const float* W2 = (const float*)d_in[7];
    const float* b2 = (const float*)d_in[8];
    const float* W3 = (const float*)d_in[9];
    const float* b3 = (const float*)d_in[10];
    float* out = (float*)d_out;

    const int SMEM_CORE  = 55296 + 52224;  // 107520 B
    const int SMEM_MPART = 2 * 52224;      // 104448 B
    cudaFuncSetAttribute(k_e_mma, cudaFuncAttributeMaxDynamicSharedMemorySize, SMEM_CORE);
    cudaFuncSetAttribute(k_final_mma, cudaFuncAttributeMaxDynamicSharedMemorySize, SMEM_CORE);
    cudaFuncSetAttribute(k_mpart_mma, cudaFuncAttributeMaxDynamicSharedMemorySize, SMEM_MPART);

    k_cvt<<<2240, 256>>>((const float4*)X, (const float4*)W1,
                         (const float4*)W2, (const float4*)W3);
    k_e_mma<<<dim3(2, 64, 2), 256, SMEM_CORE>>>(b1, b2);
    k_mpart_mma<<<dim3(2, 2, 64), 256, SMEM_MPART>>>();
    k_mreduce<<<512, 256>>>();
    k_p<<<dim3(8, 8, 2), 256>>>(W3);
    k_final_mma<<<dim3(2, 64), 256, SMEM_CORE>>>(b3, out);
}

// round 15
// speedup vs baseline: 1.3698x; 1.0993x over previous
#include <cuda_runtime.h>
#include <cuda_bf16.h>
#include <cuda_fp16.h>

#define NEDGE 8192
#define DD    256
#define SPLITK 32

typedef __nv_bfloat16 bf16;
typedef unsigned int u32;

// ---------------- scratch (device globals; no allocation allowed) ----------
__device__ __align__(16) half g_X16h[NEDGE * DD], g_X16l[NEDGE * DD]; // fp16 2-term X
__device__ __align__(16) half g_e16h[2][NEDGE * DD], g_e16l[2][NEDGE * DD];
__device__ __align__(16) half g_W116[DD * DD], g_W216[DD * DD];
__device__ __align__(16) half g_W3a16[DD * DD];
__device__ __align__(16) half g_P16[2][DD * DD];
__device__ __align__(16) half g_MpartH[2][SPLITK][DD * DD];           // fp16 partials (8 MB)
__device__ float g_M[2][DD * DD];

// ---------------- helpers ---------------------------------------------------
__device__ __forceinline__ void cpa16(void* dst, const void* src) {
    unsigned s = (unsigned)__cvta_generic_to_shared(dst);
    asm volatile("cp.async.cg.shared.global [%0], [%1], 16;" :: "r"(s), "l"(src));
}
__device__ __forceinline__ void cpa_commit() { asm volatile("cp.async.commit_group;"); }
__device__ __forceinline__ void cpa_wait0()  { asm volatile("cp.async.wait_group 0;"); }
__device__ __forceinline__ void cpa_wait1()  { asm volatile("cp.async.wait_group 1;"); }

__device__ __forceinline__ unsigned saddr(const void* p) {
    return (unsigned)__cvta_generic_to_shared(p);
}
__device__ __forceinline__ void ldsm_x4(u32* r, unsigned a) {
    asm volatile("ldmatrix.sync.aligned.m8n8.x4.shared.b16 {%0,%1,%2,%3}, [%4];"
        : "=r"(r[0]), "=r"(r[1]), "=r"(r[2]), "=r"(r[3]) : "r"(a));
}
__device__ __forceinline__ void ldsm_x4_t(u32* r, unsigned a) {
    asm volatile("ldmatrix.sync.aligned.m8n8.x4.trans.shared.b16 {%0,%1,%2,%3}, [%4];"
        : "=r"(r[0]), "=r"(r[1]), "=r"(r[2]), "=r"(r[3]) : "r"(a));
}
__device__ __forceinline__ void mma_f16(float* d, const u32* a, const u32* b) {
    asm volatile(
        "mma.sync.aligned.m16n8k16.row.col.f32.f16.f16.f32 "
        "{%0,%1,%2,%3}, {%4,%5,%6,%7}, {%8,%9}, {%0,%1,%2,%3};"
        : "+f"(d[0]), "+f"(d[1]), "+f"(d[2]), "+f"(d[3])
        : "r"(a[0]), "r"(a[1]), "r"(a[2]), "r"(a[3]), "r"(b[0]), "r"(b[1]));
}
__device__ __forceinline__ void split_store_h(half* Hp, half* Lp, size_t off,
                                              float v0, float v1) {
    half h0 = __float2half_rn(v0), h1 = __float2half_rn(v1);
    half l0 = __float2half_rn(v0 - __half2float(h0));
    half l1 = __float2half_rn(v1 - __half2float(h1));
    half2 H; H.x = h0; H.y = h1;
    half2 L; L.x = l0; L.y = l1;
    *reinterpret_cast<half2*>(Hp + off) = H;
    *reinterpret_cast<half2*>(Lp + off) = L;
}

// ===========================================================================
// k_cvt: X -> fp16 hi/lo; W1, W2, W3a -> fp16 single. grid 2240 x 256.
// ===========================================================================
__global__ void k_cvt(const float4* __restrict__ X4, const float4* __restrict__ W14,
                      const float4* __restrict__ W24, const float4* __restrict__ W34)
{
    const int idx = blockIdx.x * 256 + threadIdx.x;
    if (idx < 524288) {
        const float4 v = X4[idx];
        const size_t o = (size_t)idx * 4;
        split_store_h(g_X16h, g_X16l, o,     v.x, v.y);
        split_store_h(g_X16h, g_X16l, o + 2, v.z, v.w);
    } else {
        const int w = idx - 524288;
        const int which = w >> 14;
        const int off4 = w & 16383;
        const size_t o = (size_t)off4 * 4;
        const float4 v = (which == 0) ? W14[off4] : (which == 1) ? W24[off4] : W34[off4];
        half* dst = (which == 0) ? g_W116 : (which == 1) ? g_W216 : g_W3a16;
        half2 a; a.x = __float2half_rn(v.x); a.y = __float2half_rn(v.y);
        half2 b; b.x = __float2half_rn(v.z); b.y = __float2half_rn(v.w);
        *reinterpret_cast<half2*>(dst + o)     = a;
        *reinterpret_cast<half2*>(dst + o + 2) = b;
    }
}

// ===========================================================================
// Core: multi-pass fp16 MMA GEMM. Block tile 128x128, 8 warps (2m x 4n),
// warp tile 64x32, k-tile 64, 3-stage cp.async ring. smem 107520 B.
// ===========================================================================
#define AS_ELEM(b, r, c) sAs[(b) * 9216 + (r) * 72 + (c)]
#define BS_ELEM(b, r, c) sBs[(b) * 8704 + (r) * 136 + (c)]

template <int NPASS>
__device__ __forceinline__ void mma_core_rowA(
    const half* const* Ap, const half* const* Bp,
    int rowBase, int colBase, float (&acc)[4][4][4])
{
    extern __shared__ __align__(16) char sm_raw[];
    half* sAs = (half*)sm_raw;
    half* sBs = (half*)(sm_raw + 55296);

    const int tid = threadIdx.x;
    const int lane = tid & 31, w = tid >> 5;
    const int m0w = (w >> 2) * 64, n0w = (w & 3) * 32;

    auto prefetch = [&](int it, int bufn) {
        const int pass = it >> 2;
        const int k0 = (it & 3) * 64;
        const half* __restrict__ A = Ap[pass];
        const half* __restrict__ B = Bp[pass];
#pragma unroll
        for (int i = 0; i < 4; ++i) {
            const int ca = tid + 256 * i;               // A: 128 rows x 64 k
            const int ar = ca >> 3, ao = (ca & 7) * 8;
            cpa16(&AS_ELEM(bufn, ar, ao), A + (size_t)(rowBase + ar) * DD + k0 + ao);
            const int cb = tid + 256 * i;               // B: 64 k x 128 n
            const int br = cb >> 4, bo = (cb & 15) * 8;
            cpa16(&BS_ELEM(bufn, br, bo), B + (size_t)(k0 + br) * DD + colBase + bo);
        }
        cpa_commit();
    };

    const int t = lane >> 3;
    const int aro = (t & 1) * 8 + (lane & 7);
    const int aco = (t >> 1) * 8;
    const int bro2 = (lane & 7) + ((lane >> 3) & 1) * 8;
    const int bco2 = (lane >> 4) * 8;

    constexpr int NIT = NPASS * 4;
    prefetch(0, 0);
    prefetch(1, 1);
    for (int it = 0; it < NIT; ++it) {
        cpa_wait1();
        __syncthreads();
        if (it + 2 < NIT) prefetch(it + 2, (it + 2) % 3);
        else cpa_commit();   // keep wait-group arithmetic exact
        const int buf = it % 3;
#pragma unroll
        for (int ki = 0; ki < 4; ++ki) {
            u32 a[4][4], bq[2][4];
#pragma unroll
            for (int mi = 0; mi < 4; ++mi)
                ldsm_x4(a[mi], saddr(&AS_ELEM(buf, m0w + mi * 16 + aro, ki * 16 + aco)));
#pragma unroll
            for (int nj = 0; nj < 2; ++nj)
                ldsm_x4_t(bq[nj], saddr(&BS_ELEM(buf, ki * 16 + bro2, n0w + nj * 16 + bco2)));
#pragma unroll
            for (int mi = 0; mi < 4; ++mi)
#pragma unroll
                for (int ni = 0; ni < 4; ++ni)
                    mma_f16(acc[mi][ni], a[mi], &bq[ni >> 1][(ni & 1) * 2]);
        }
    }
}

// ===========================================================================
// k_e_mma: e_z = relu(X @ W_z + b_z). FP16 2-pass: (X16h + X16l) @ W16_z.
// Output fp16 hi/lo. grid (2, 64, 2) x 256.
// ===========================================================================
__global__ void __launch_bounds__(256, 2)
k_e_mma(const float* __restrict__ b1, const float* __restrict__ b2)
{
    const int z = blockIdx.z;
    const half* Wz = z ? g_W216 : g_W116;
    const half* Ap[2] = {g_X16h, g_X16l};
    const half* Bp[2] = {Wz, Wz};
    const float* __restrict__ bias = z ? b2 : b1;
    half* __restrict__ Eh = g_e16h[z];
    half* __restrict__ El = g_e16l[z];

    const int rowBase = blockIdx.y * 128, colBase = blockIdx.x * 128;
    float acc[4][4][4] = {};
    mma_core_rowA<2>(Ap, Bp, rowBase, colBase, acc);

    const int lane = threadIdx.x & 31, w = threadIdx.x >> 5;
    const int m0w = (w >> 2) * 64, n0w = (w & 3) * 32;
    const int r_l = lane >> 2, c_l = (lane & 3) * 2;
#pragma unroll
    for (int mi = 0; mi < 4; ++mi)
#pragma unroll
        for (int ni = 0; ni < 4; ++ni) {
            const int col = colBase + n0w + ni * 8 + c_l;
            const float2 bb = *(const float2*)&bias[col];
#pragma unroll
            for (int h = 0; h < 2; ++h) {
                const int r = rowBase + m0w + mi * 16 + r_l + h * 8;
                float v0 = fmaxf(acc[mi][ni][h * 2 + 0] + bb.x, 0.f);
                float v1 = fmaxf(acc[mi][ni][h * 2 + 1] + bb.y, 0.f);
                split_store_h(Eh, El, (size_t)r * DD + col, v0, v1);
            }
        }
}

// ===========================================================================
// k_mpart_mma: split-K partials of M_z = e_zᵀ @ X. FP16 2-pass:
// (e16h + e16l)ᵀ · X16h. Output fp16 partials. grid (2, 2, 64) x 256.
// ===========================================================================
#define ES_ELEM(b, r, c) sEs[(b) * 8704 + (r) * 136 + (c)]
#define XS_ELEM(b, r, c) sXs[(b) * 8704 + (r) * 136 + (c)]

__global__ void __launch_bounds__(256, 2)
k_mpart_mma()
{
    const int mat = blockIdx.z >> 5, split = blockIdx.z & 31;
    const half* Ap[2] = {g_e16h[mat], g_e16l[mat]};
    half* __restrict__ Cp = g_MpartH[mat][split];

    extern __shared__ __align__(16) char sm_raw[];
    half* sEs = (half*)sm_raw;
    half* sXs = (half*)(sm_raw + 52224);

    const int tid = threadIdx.x;
    const int lane = tid & 31, w = tid >> 5;
    const int m0w = (w >> 2) * 64, n0w = (w & 3) * 32;
    const int mBase = blockIdx.y * 128, nBase = blockIdx.x * 128;
    const int i0 = split * (NEDGE / SPLITK);   // 256-edge chunk

    auto prefetch = [&](int it, int bufn) {
        const int pass = it >> 2;
        const int e0 = i0 + (it & 3) * 64;
        const half* __restrict__ E = Ap[pass];
#pragma unroll
        for (int i = 0; i < 4; ++i) {
            const int c = tid + 256 * i;                // 64 rows x 128 cols
            const int r = c >> 4, o = (c & 15) * 8;
            cpa16(&ES_ELEM(bufn, r, o), E + (size_t)(e0 + r) * DD + mBase + o);
            cpa16(&XS_ELEM(bufn, r, o), g_X16h + (size_t)(e0 + r) * DD + nBase + o);
        }
        cpa_commit();
    };

    const int t = lane >> 3;
    const int akro = (t >> 1) * 8 + (lane & 7);
    const int amco = (t & 1) * 8;
    const int bro2 = (lane & 7) + ((lane >> 3) & 1) * 8;
    const int bco2 = (lane >> 4) * 8;

    float acc[4][4][4] = {};
    prefetch(0, 0);
    prefetch(1, 1);
    for (int it = 0; it < 8; ++it) {
        cpa_wait1();
        __syncthreads();
        if (it + 2 < 8) prefetch(it + 2, (it + 2) % 3);
        else cpa_commit();
        const int buf = it % 3;
#pragma unroll
        for (int ki = 0; ki < 4; ++ki) {
            u32 a[4][4], bq[2][4];
#pragma unroll
            for (int mi = 0; mi < 4; ++mi)
                ldsm_x4_t(a[mi], saddr(&ES_ELEM(buf, ki * 16 + akro, m0w + mi * 16 + amco)));
#pragma unroll
            for (int nj = 0; nj < 2; ++nj)
                ldsm_x4_t(bq[nj], saddr(&XS_ELEM(buf, ki * 16 + bro2, n0w + nj * 16 + bco2)));
#pragma unroll
            for (int mi = 0; mi < 4; ++mi)
#pragma unroll
                for (int ni = 0; ni < 4; ++ni)
                    mma_f16(acc[mi][ni], a[mi], &bq[ni >> 1][(ni & 1) * 2]);
        }
    }

    const int r_l = lane >> 2, c_l = (lane & 3) * 2;
#pragma unroll
    for (int mi = 0; mi < 4; ++mi)
#pragma unroll
        for (int ni = 0; ni < 4; ++ni) {
            const int col = nBase + n0w + ni * 8 + c_l;
#pragma unroll
            for (int h = 0; h < 2; ++h) {
                const int r = mBase + m0w + mi * 16 + r_l + h * 8;
                half2 v;
                v.x = __float2half_rn(acc[mi][ni][h * 2 + 0]);
                v.y = __float2half_rn(acc[mi][ni][h * 2 + 1]);
                *reinterpret_cast<half2*>(&Cp[(size_t)r * DD + col]) = v;
            }
        }
}

// ===========================================================================
// k_mreduce: 4-thread split over 32 fp16 partials (8 each) + shfl_xor tree,
// fp32 accumulation. grid 512 x 256.
// ===========================================================================
__global__ void k_mreduce()
{
    const int gid = blockIdx.x * 256 + threadIdx.x;   // 0..131071
    const int q8 = (gid & 3) * 8;
    const int o = gid >> 2;                           // 0..32767
    const int mat = o >> 14;
    const int o4 = (o & 16383) * 4;
    float4 s = make_float4(0.f, 0.f, 0.f, 0.f);
#pragma unroll
    for (int p = 0; p < 8; p++) {
        const half2* src = reinterpret_cast<const half2*>(&g_MpartH[mat][q8 + p][o4]);
        const float2 lo = __half22float2(src[0]);
        const float2 hi = __half22float2(src[1]);
        s.x += lo.x; s.y += lo.y; s.z += hi.x; s.w += hi.y;
    }
#pragma unroll
    for (int d = 1; d <= 2; d <<= 1) {
        s.x += __shfl_xor_sync(0xffffffffu, s.x, d);
        s.y += __shfl_xor_sync(0xffffffffu, s.y, d);
        s.z += __shfl_xor_sync(0xffffffffu, s.z, d);
        s.w += __shfl_xor_sync(0xffffffffu, s.w, d);
    }
    if ((gid & 3) == 0) {
        const float sc = 1.0f / DD;
        s.x *= sc; s.y *= sc; s.z *= sc; s.w *= sc;
        *(float4*)&g_M[mat][o4] = s;
    }
}

// ===========================================================================
// k_p: P_z = M_z @ W3b_z (fp32, K=256 sequential), emits fp16 P.
// 32x32 out tile, grid (8, 8, 2) x 256.
// ===========================================================================
__global__ void k_p(const float* __restrict__ W3)
{
    const int mat = blockIdx.z;
    const float* __restrict__ A = g_M[mat];
    const float* __restrict__ B = W3 + (size_t)(DD + mat * DD) * DD;

    __shared__ __align__(16) float As[32][68];
    __shared__ __align__(16) float Bs[64][36];

    const int tid = threadIdx.x;
    const int mBase = blockIdx.y * 32, nBase = blockIdx.x * 32;
    const int ty = tid >> 4, tx = tid & 15;

    float a00 = 0.f, a01 = 0.f, a10 = 0.f, a11 = 0.f;

    for (int kt = 0; kt < DD; kt += 64) {
        const int c0 = tid, c1 = tid + 256;
        cpa16(&As[c0 >> 4][(c0 & 15) * 4], &A[(size_t)(mBase + (c0 >> 4)) * DD + kt + (c0 & 15) * 4]);
        cpa16(&As[c1 >> 4][(c1 & 15) * 4], &A[(size_t)(mBase + (c1 >> 4)) * DD + kt + (c1 & 15) * 4]);
        cpa16(&Bs[c0 >> 3][(c0 & 7) * 4], &B[(size_t)(kt + (c0 >> 3)) * DD + nBase + (c0 & 7) * 4]);
        cpa16(&Bs[c1 >> 3][(c1 & 7) * 4], &B[(size_t)(kt + (c1 >> 3)) * DD + nBase + (c1 & 7) * 4]);
        cpa_commit(); cpa_wait0();
        __syncthreads();
#pragma unroll
        for (int kk = 0; kk < 64; kk++) {
            const float av0 = As[ty * 2 + 0][kk];
            const float av1 = As[ty * 2 + 1][kk];
            const float2 bv = *(const float2*)&Bs[kk][tx * 2];
            a00 = fmaf(av0, bv.x, a00); a01 = fmaf(av0, bv.y, a01);
            a10 = fmaf(av1, bv.x, a10); a11 = fmaf(av1, bv.y, a11);
        }
        __syncthreads();
    }

    half2 r0; r0.x = __float2half_rn(a00); r0.y = __float2half_rn(a01);
    half2 r1; r1.x = __float2half_rn(a10); r1.y = __float2half_rn(a11);
    *reinterpret_cast<half2*>(&g_P16[mat][(size_t)(mBase + ty * 2 + 0) * DD + nBase + tx * 2]) = r0;
    *reinterpret_cast<half2*>(&g_P16[mat][(size_t)(mBase + ty * 2 + 1) * DD + nBase + tx * 2]) = r1;
}

// ===========================================================================
// k_final_mma: out = relu(X@W3a + e1@P1 + e2@P2 + b3). FP16 5-pass:
// X16h·W3a16 + (e16h+e16l)·P16 per mat. grid (2, 64) x 256.
// ===========================================================================
__global__ void __launch_bounds__(256, 2)
k_final_mma(const float* __restrict__ b3, float* __restrict__ out)
{
    const half* Ap[5] = {g_X16h,
                         g_e16h[0], g_e16l[0],
                         g_e16h[1], g_e16l[1]};
    const half* Bp[5] = {g_W3a16,
                         g_P16[0], g_P16[0],
                         g_P16[1], g_P16[1]};

    const int rowBase = blockIdx.y * 128, colBase = blockIdx.x * 128;
    float acc[4][4][4] = {};
    mma_core_rowA<5>(Ap, Bp, rowBase, colBase, acc);

    const int lane = threadIdx.x & 31, w = threadIdx.x >> 5;
    const int m0w = (w >> 2) * 64, n0w = (w & 3) * 32;
    const int r_l = lane >> 2, c_l = (lane & 3) * 2;
#pragma unroll
    for (int mi = 0; mi < 4; ++mi)
#pragma unroll
        for (int ni = 0; ni < 4; ++ni) {
            const int col = colBase + n0w + ni * 8 + c_l;
            const float2 bb = *(const float2*)&b3[col];
#pragma unroll
            for (int h = 0; h < 2; ++h) {
                const int r = rowBase + m0w + mi * 16 + r_l + h * 8;
                float2 v;
                v.x = fmaxf(acc[mi][ni][h * 2 + 0] + bb.x, 0.f);
                v.y = fmaxf(acc[mi][ni][h * 2 + 1] + bb.y, 0.f);
                *(float2*)&out[(size_t)r * DD + col] = v;
            }
        }
}

// ---------------------------------------------------------------------------
// Inputs (metadata order):
// 0 edge_pred[8192] f32 | 1 edge_corner[8192,2] i64 | 2 all_corners[4096,2] f32
// 3 edge_x[8192,256] f32 | 4 image_x[1024] f32 | 5 W1[256,256] | 6 b1[256]
// 7 W2[256,256] | 8 b2[256] | 9 W3[768,256] | 10 b3[256]
// Output: [8192, 256] f32
// ---------------------------------------------------------------------------
extern "C" void kernel_launch(void* const* d_in, const int* in_sizes, int n_in,
                              void* d_out, int out_size)
{
    (void)in_sizes; (void)n_in; (void)out_size;
    const float* X  = (const float*)d_in[3];
    const float* W1 = (const float*)d_in[5];
    const float* b1 = (const float*)d_in[6];
    const float* W2 = (const float*)d_in[7];
    const float* b2 = (const float*)d_in[8];
    const float* W3 = (const float*)d_in[9];
    const float* b3 = (const float*)d_in[10];
    float* out = (float*)d_out;

    const int SMEM_CORE  = 55296 + 52224;  // 107520 B
    const int SMEM_MPART = 2 * 52224;      // 104448 B
    cudaFuncSetAttribute(k_e_mma, cudaFuncAttributeMaxDynamicSharedMemorySize, SMEM_CORE);
    cudaFuncSetAttribute(k_final_mma, cudaFuncAttributeMaxDynamicSharedMemorySize, SMEM_CORE);
    cudaFuncSetAttribute(k_mpart_mma, cudaFuncAttributeMaxDynamicSharedMemorySize, SMEM_MPART);

    k_cvt<<<2240, 256>>>((const float4*)X, (const float4*)W1,
                         (const float4*)W2, (const float4*)W3);
    k_e_mma<<<dim3(2, 64, 2), 256, SMEM_CORE>>>(b1, b2);
    k_mpart_mma<<<dim3(2, 2, 64), 256, SMEM_MPART>>>();
    k_mreduce<<<512, 256>>>();
    k_p<<<dim3(8, 8, 2), 256>>>(W3);
    k_final_mma<<<dim3(2, 64), 256, SMEM_CORE>>>(b3, out);
}

// round 16
// speedup vs baseline: 2.0132x; 1.4697x over previous
#include <cuda_runtime.h>
#include <cuda_fp16.h>

#define NEDGE 8192
#define DD    256
#define SPLITK 32

typedef unsigned int u32;

// ---------------- scratch (device globals; no allocation allowed) ----------
__device__ __align__(16) half g_X16[NEDGE * DD];
__device__ __align__(16) half g_e16[2][NEDGE * DD];
__device__ __align__(16) half g_W116[DD * DD], g_W216[DD * DD];
__device__ __align__(16) half g_W3a16[DD * DD];
__device__ __align__(16) half g_P16[2][DD * DD];
__device__ __align__(16) half g_MpartH[2][SPLITK][DD * DD];
__device__ float g_M[2][DD * DD];

// ---------------- helpers ---------------------------------------------------
__device__ __forceinline__ void cpa16(void* dst, const void* src) {
    unsigned s = (unsigned)__cvta_generic_to_shared(dst);
    asm volatile("cp.async.cg.shared.global [%0], [%1], 16;" :: "r"(s), "l"(src));
}
__device__ __forceinline__ void cpa_commit() { asm volatile("cp.async.commit_group;"); }
__device__ __forceinline__ void cpa_wait0()  { asm volatile("cp.async.wait_group 0;"); }
__device__ __forceinline__ void cpa_wait1()  { asm volatile("cp.async.wait_group 1;"); }

__device__ __forceinline__ unsigned saddr(const void* p) {
    return (unsigned)__cvta_generic_to_shared(p);
}
__device__ __forceinline__ void ldsm_x4(u32* r, unsigned a) {
    asm volatile("ldmatrix.sync.aligned.m8n8.x4.shared.b16 {%0,%1,%2,%3}, [%4];"
        : "=r"(r[0]), "=r"(r[1]), "=r"(r[2]), "=r"(r[3]) : "r"(a));
}
__device__ __forceinline__ void ldsm_x4_t(u32* r, unsigned a) {
    asm volatile("ldmatrix.sync.aligned.m8n8.x4.trans.shared.b16 {%0,%1,%2,%3}, [%4];"
        : "=r"(r[0]), "=r"(r[1]), "=r"(r[2]), "=r"(r[3]) : "r"(a));
}
__device__ __forceinline__ void mma_f16(float* d, const u32* a, const u32* b) {
    asm volatile(
        "mma.sync.aligned.m16n8k16.row.col.f32.f16.f16.f32 "
        "{%0,%1,%2,%3}, {%4,%5,%6,%7}, {%8,%9}, {%0,%1,%2,%3};"
        : "+f"(d[0]), "+f"(d[1]), "+f"(d[2]), "+f"(d[3])
        : "r"(a[0]), "r"(a[1]), "r"(a[2]), "r"(a[3]), "r"(b[0]), "r"(b[1]));
}

// ===========================================================================
// k_cvt: X, W1, W2, W3a -> single fp16. grid 2240 x 256.
// ===========================================================================
__global__ void k_cvt(const float4* __restrict__ X4, const float4* __restrict__ W14,
                      const float4* __restrict__ W24, const float4* __restrict__ W34)
{
    const int idx = blockIdx.x * 256 + threadIdx.x;
    float4 v;
    half* dst;
    size_t o;
    if (idx < 524288) {
        v = X4[idx];
        dst = g_X16;
        o = (size_t)idx * 4;
    } else {
        const int w = idx - 524288;
        const int which = w >> 14;
        const int off4 = w & 16383;
        v = (which == 0) ? W14[off4] : (which == 1) ? W24[off4] : W34[off4];
        dst = (which == 0) ? g_W116 : (which == 1) ? g_W216 : g_W3a16;
        o = (size_t)off4 * 4;
    }
    half2 a; a.x = __float2half_rn(v.x); a.y = __float2half_rn(v.y);
    half2 b; b.x = __float2half_rn(v.z); b.y = __float2half_rn(v.w);
    *reinterpret_cast<half2*>(dst + o)     = a;
    *reinterpret_cast<half2*>(dst + o + 2) = b;
}

// ===========================================================================
// Core: multi-pass fp16 MMA GEMM. Block tile 128x128, 8 warps (2m x 4n),
// warp tile 64x32, k-tile 64, 3-stage cp.async ring. smem 107520 B.
// ===========================================================================
#define AS_ELEM(b, r, c) sAs[(b) * 9216 + (r) * 72 + (c)]
#define BS_ELEM(b, r, c) sBs[(b) * 8704 + (r) * 136 + (c)]

template <int NPASS>
__device__ __forceinline__ void mma_core_rowA(
    const half* const* Ap, const half* const* Bp,
    int rowBase, int colBase, float (&acc)[4][4][4])
{
    extern __shared__ __align__(16) char sm_raw[];
    half* sAs = (half*)sm_raw;
    half* sBs = (half*)(sm_raw + 55296);

    const int tid = threadIdx.x;
    const int lane = tid & 31, w = tid >> 5;
    const int m0w = (w >> 2) * 64, n0w = (w & 3) * 32;

    auto prefetch = [&](int it, int bufn) {
        const int pass = it >> 2;
        const int k0 = (it & 3) * 64;
        const half* __restrict__ A = Ap[pass];
        const half* __restrict__ B = Bp[pass];
#pragma unroll
        for (int i = 0; i < 4; ++i) {
            const int ca = tid + 256 * i;               // A: 128 rows x 64 k
            const int ar = ca >> 3, ao = (ca & 7) * 8;
            cpa16(&AS_ELEM(bufn, ar, ao), A + (size_t)(rowBase + ar) * DD + k0 + ao);
            const int cb = tid + 256 * i;               // B: 64 k x 128 n
            const int br = cb >> 4, bo = (cb & 15) * 8;
            cpa16(&BS_ELEM(bufn, br, bo), B + (size_t)(k0 + br) * DD + colBase + bo);
        }
        cpa_commit();
    };

    const int t = lane >> 3;
    const int aro = (t & 1) * 8 + (lane & 7);
    const int aco = (t >> 1) * 8;
    const int bro2 = (lane & 7) + ((lane >> 3) & 1) * 8;
    const int bco2 = (lane >> 4) * 8;

    constexpr int NIT = NPASS * 4;
    prefetch(0, 0);
    prefetch(1, 1);
    for (int it = 0; it < NIT; ++it) {
        cpa_wait1();
        __syncthreads();
        if (it + 2 < NIT) prefetch(it + 2, (it + 2) % 3);
        else cpa_commit();   // keep wait-group arithmetic exact
        const int buf = it % 3;
#pragma unroll
        for (int ki = 0; ki < 4; ++ki) {
            u32 a[4][4], bq[2][4];
#pragma unroll
            for (int mi = 0; mi < 4; ++mi)
                ldsm_x4(a[mi], saddr(&AS_ELEM(buf, m0w + mi * 16 + aro, ki * 16 + aco)));
#pragma unroll
            for (int nj = 0; nj < 2; ++nj)
                ldsm_x4_t(bq[nj], saddr(&BS_ELEM(buf, ki * 16 + bro2, n0w + nj * 16 + bco2)));
#pragma unroll
            for (int mi = 0; mi < 4; ++mi)
#pragma unroll
                for (int ni = 0; ni < 4; ++ni)
                    mma_f16(acc[mi][ni], a[mi], &bq[ni >> 1][(ni & 1) * 2]);
        }
    }
}

// ===========================================================================
// k_e_mma: e_z = relu(X16 @ W16_z + b_z) -> fp16. 1 pass. grid (2, 64, 2).
// ===========================================================================
__global__ void __launch_bounds__(256, 2)
k_e_mma(const float* __restrict__ b1, const float* __restrict__ b2)
{
    const int z = blockIdx.z;
    const half* Ap[1] = {g_X16};
    const half* Bp[1] = {z ? g_W216 : g_W116};
    const float* __restrict__ bias = z ? b2 : b1;
    half* __restrict__ E = g_e16[z];

    const int rowBase = blockIdx.y * 128, colBase = blockIdx.x * 128;
    float acc[4][4][4] = {};
    mma_core_rowA<1>(Ap, Bp, rowBase, colBase, acc);

    const int lane = threadIdx.x & 31, w = threadIdx.x >> 5;
    const int m0w = (w >> 2) * 64, n0w = (w & 3) * 32;
    const int r_l = lane >> 2, c_l = (lane & 3) * 2;
#pragma unroll
    for (int mi = 0; mi < 4; ++mi)
#pragma unroll
        for (int ni = 0; ni < 4; ++ni) {
            const int col = colBase + n0w + ni * 8 + c_l;
            const float2 bb = *(const float2*)&bias[col];
#pragma unroll
            for (int h = 0; h < 2; ++h) {
                const int r = rowBase + m0w + mi * 16 + r_l + h * 8;
                half2 v;
                v.x = __float2half_rn(fmaxf(acc[mi][ni][h * 2 + 0] + bb.x, 0.f));
                v.y = __float2half_rn(fmaxf(acc[mi][ni][h * 2 + 1] + bb.y, 0.f));
                *reinterpret_cast<half2*>(&E[(size_t)r * DD + col]) = v;
            }
        }
}

// ===========================================================================
// k_mpart_mma: split-K partials of M_z = e16_zᵀ @ X16. 1 pass, NIT = 4.
// fp16 partials out. grid (2, 2, 64) x 256.
// ===========================================================================
#define ES_ELEM(b, r, c) sEs[(b) * 8704 + (r) * 136 + (c)]
#define XS_ELEM(b, r, c) sXs[(b) * 8704 + (r) * 136 + (c)]

__global__ void __launch_bounds__(256, 2)
k_mpart_mma()
{
    const int mat = blockIdx.z >> 5, split = blockIdx.z & 31;
    const half* __restrict__ E = g_e16[mat];
    half* __restrict__ Cp = g_MpartH[mat][split];

    extern __shared__ __align__(16) char sm_raw[];
    half* sEs = (half*)sm_raw;
    half* sXs = (half*)(sm_raw + 52224);

    const int tid = threadIdx.x;
    const int lane = tid & 31, w = tid >> 5;
    const int m0w = (w >> 2) * 64, n0w = (w & 3) * 32;
    const int mBase = blockIdx.y * 128, nBase = blockIdx.x * 128;
    const int i0 = split * (NEDGE / SPLITK);   // 256-edge chunk

    auto prefetch = [&](int it, int bufn) {
        const int e0 = i0 + it * 64;
#pragma unroll
        for (int i = 0; i < 4; ++i) {
            const int c = tid + 256 * i;                // 64 rows x 128 cols
            const int r = c >> 4, o = (c & 15) * 8;
            cpa16(&ES_ELEM(bufn, r, o), E + (size_t)(e0 + r) * DD + mBase + o);
            cpa16(&XS_ELEM(bufn, r, o), g_X16 + (size_t)(e0 + r) * DD + nBase + o);
        }
        cpa_commit();
    };

    const int t = lane >> 3;
    const int akro = (t >> 1) * 8 + (lane & 7);
    const int amco = (t & 1) * 8;
    const int bro2 = (lane & 7) + ((lane >> 3) & 1) * 8;
    const int bco2 = (lane >> 4) * 8;

    float acc[4][4][4] = {};
    prefetch(0, 0);
    prefetch(1, 1);
    for (int it = 0; it < 4; ++it) {
        cpa_wait1();
        __syncthreads();
        if (it + 2 < 4) prefetch(it + 2, (it + 2) % 3);
        else cpa_commit();
        const int buf = it % 3;
#pragma unroll
        for (int ki = 0; ki < 4; ++ki) {
            u32 a[4][4], bq[2][4];
#pragma unroll
            for (int mi = 0; mi < 4; ++mi)
                ldsm_x4_t(a[mi], saddr(&ES_ELEM(buf, ki * 16 + akro, m0w + mi * 16 + amco)));
#pragma unroll
            for (int nj = 0; nj < 2; ++nj)
                ldsm_x4_t(bq[nj], saddr(&XS_ELEM(buf, ki * 16 + bro2, n0w + nj * 16 + bco2)));
#pragma unroll
            for (int mi = 0; mi < 4; ++mi)
#pragma unroll
                for (int ni = 0; ni < 4; ++ni)
                    mma_f16(acc[mi][ni], a[mi], &bq[ni >> 1][(ni & 1) * 2]);
        }
    }

    const int r_l = lane >> 2, c_l = (lane & 3) * 2;
#pragma unroll
    for (int mi = 0; mi < 4; ++mi)
#pragma unroll
        for (int ni = 0; ni < 4; ++ni) {
            const int col = nBase + n0w + ni * 8 + c_l;
#pragma unroll
            for (int h = 0; h < 2; ++h) {
                const int r = mBase + m0w + mi * 16 + r_l + h * 8;
                half2 v;
                v.x = __float2half_rn(acc[mi][ni][h * 2 + 0]);
                v.y = __float2half_rn(acc[mi][ni][h * 2 + 1]);
                *reinterpret_cast<half2*>(&Cp[(size_t)r * DD + col]) = v;
            }
        }
}

// ===========================================================================
// k_mreduce: 4-thread split over 32 fp16 partials (8 each) + shfl_xor tree,
// fp32 accumulation. grid 512 x 256.
// ===========================================================================
__global__ void k_mreduce()
{
    const int gid = blockIdx.x * 256 + threadIdx.x;   // 0..131071
    const int q8 = (gid & 3) * 8;
    const int o = gid >> 2;                           // 0..32767
    const int mat = o >> 14;
    const int o4 = (o & 16383) * 4;
    float4 s = make_float4(0.f, 0.f, 0.f, 0.f);
#pragma unroll
    for (int p = 0; p < 8; p++) {
        const half2* src = reinterpret_cast<const half2*>(&g_MpartH[mat][q8 + p][o4]);
        const float2 lo = __half22float2(src[0]);
        const float2 hi = __half22float2(src[1]);
        s.x += lo.x; s.y += lo.y; s.z += hi.x; s.w += hi.y;
    }
#pragma unroll
    for (int d = 1; d <= 2; d <<= 1) {
        s.x += __shfl_xor_sync(0xffffffffu, s.x, d);
        s.y += __shfl_xor_sync(0xffffffffu, s.y, d);
        s.z += __shfl_xor_sync(0xffffffffu, s.z, d);
        s.w += __shfl_xor_sync(0xffffffffu, s.w, d);
    }
    if ((gid & 3) == 0) {
        const float sc = 1.0f / DD;
        s.x *= sc; s.y *= sc; s.z *= sc; s.w *= sc;
        *(float4*)&g_M[mat][o4] = s;
    }
}

// ===========================================================================
// k_p: P_z = M_z @ W3b_z (fp32, K=256 sequential), emits fp16 P.
// 32x32 out tile, grid (8, 8, 2) x 256.
// ===========================================================================
__global__ void k_p(const float* __restrict__ W3)
{
    const int mat = blockIdx.z;
    const float* __restrict__ A = g_M[mat];
    const float* __restrict__ B = W3 + (size_t)(DD + mat * DD) * DD;

    __shared__ __align__(16) float As[32][68];
    __shared__ __align__(16) float Bs[64][36];

    const int tid = threadIdx.x;
    const int mBase = blockIdx.y * 32, nBase = blockIdx.x * 32;
    const int ty = tid >> 4, tx = tid & 15;

    float a00 = 0.f, a01 = 0.f, a10 = 0.f, a11 = 0.f;

    for (int kt = 0; kt < DD; kt += 64) {
        const int c0 = tid, c1 = tid + 256;
        cpa16(&As[c0 >> 4][(c0 & 15) * 4], &A[(size_t)(mBase + (c0 >> 4)) * DD + kt + (c0 & 15) * 4]);
        cpa16(&As[c1 >> 4][(c1 & 15) * 4], &A[(size_t)(mBase + (c1 >> 4)) * DD + kt + (c1 & 15) * 4]);
        cpa16(&Bs[c0 >> 3][(c0 & 7) * 4], &B[(size_t)(kt + (c0 >> 3)) * DD + nBase + (c0 & 7) * 4]);
        cpa16(&Bs[c1 >> 3][(c1 & 7) * 4], &B[(size_t)(kt + (c1 >> 3)) * DD + nBase + (c1 & 7) * 4]);
        cpa_commit(); cpa_wait0();
        __syncthreads();
#pragma unroll
        for (int kk = 0; kk < 64; kk++) {
            const float av0 = As[ty * 2 + 0][kk];
            const float av1 = As[ty * 2 + 1][kk];
            const float2 bv = *(const float2*)&Bs[kk][tx * 2];
            a00 = fmaf(av0, bv.x, a00); a01 = fmaf(av0, bv.y, a01);
            a10 = fmaf(av1, bv.x, a10); a11 = fmaf(av1, bv.y, a11);
        }
        __syncthreads();
    }

    half2 r0; r0.x = __float2half_rn(a00); r0.y = __float2half_rn(a01);
    half2 r1; r1.x = __float2half_rn(a10); r1.y = __float2half_rn(a11);
    *reinterpret_cast<half2*>(&g_P16[mat][(size_t)(mBase + ty * 2 + 0) * DD + nBase + tx * 2]) = r0;
    *reinterpret_cast<half2*>(&g_P16[mat][(size_t)(mBase + ty * 2 + 1) * DD + nBase + tx * 2]) = r1;
}

// ===========================================================================
// k_final_mma: out = relu(X16@W3a16 + e16_1@P16_1 + e16_2@P16_2 + b3).
// 3 passes. grid (2, 64) x 256.
// ===========================================================================
__global__ void __launch_bounds__(256, 2)
k_final_mma(const float* __restrict__ b3, float* __restrict__ out)
{
    const half* Ap[3] = {g_X16, g_e16[0], g_e16[1]};
    const half* Bp[3] = {g_W3a16, g_P16[0], g_P16[1]};

    const int rowBase = blockIdx.y * 128, colBase = blockIdx.x * 128;
    float acc[4][4][4] = {};
    mma_core_rowA<3>(Ap, Bp, rowBase, colBase, acc);

    const int lane = threadIdx.x & 31, w = threadIdx.x >> 5;
    const int m0w = (w >> 2) * 64, n0w = (w & 3) * 32;
    const int r_l = lane >> 2, c_l = (lane & 3) * 2;
#pragma unroll
    for (int mi = 0; mi < 4; ++mi)
#pragma unroll
        for (int ni = 0; ni < 4; ++ni) {
            const int col = colBase + n0w + ni * 8 + c_l;
            const float2 bb = *(const float2*)&b3[col];
#pragma unroll
            for (int h = 0; h < 2; ++h) {
                const int r = rowBase + m0w + mi * 16 + r_l + h * 8;
                float2 v;
                v.x = fmaxf(acc[mi][ni][h * 2 + 0] + bb.x, 0.f);
                v.y = fmaxf(acc[mi][ni][h * 2 + 1] + bb.y, 0.f);
                *(float2*)&out[(size_t)r * DD + col] = v;
            }
        }
}

// ---------------------------------------------------------------------------
// Inputs (metadata order):
// 0 edge_pred[8192] f32 | 1 edge_corner[8192,2] i64 | 2 all_corners[4096,2] f32
// 3 edge_x[8192,256] f32 | 4 image_x[1024] f32 | 5 W1[256,256] | 6 b1[256]
// 7 W2[256,256] | 8 b2[256] | 9 W3[768,256] | 10 b3[256]
// Output: [8192, 256] f32
// ---------------------------------------------------------------------------
extern "C" void kernel_launch(void* const* d_in, const int* in_sizes, int n_in,
                              void* d_out, int out_size)
{
    (void)in_sizes; (void)n_in; (void)out_size;
    const float* X  = (const float*)d_in[3];
    const float* W1 = (const float*)d_in[5];
    const float* b1 = (const float*)d_in[6];
    const float* W2 = (const float*)d_in[7];
    const float* b2 = (const float*)d_in[8];
    const float* W3 = (const float*)d_in[9];
    const float* b3 = (const float*)d_in[10];
    float* out = (float*)d_out;

    const int SMEM_CORE  = 55296 + 52224;  // 107520 B
    const int SMEM_MPART = 2 * 52224;      // 104448 B
    cudaFuncSetAttribute(k_e_mma, cudaFuncAttributeMaxDynamicSharedMemorySize, SMEM_CORE);
    cudaFuncSetAttribute(k_final_mma, cudaFuncAttributeMaxDynamicSharedMemorySize, SMEM_CORE);
    cudaFuncSetAttribute(k_mpart_mma, cudaFuncAttributeMaxDynamicSharedMemorySize, SMEM_MPART);

    k_cvt<<<2240, 256>>>((const float4*)X, (const float4*)W1,
                         (const float4*)W2, (const float4*)W3);
    k_e_mma<<<dim3(2, 64, 2), 256, SMEM_CORE>>>(b1, b2);
    k_mpart_mma<<<dim3(2, 2, 64), 256, SMEM_MPART>>>();
    k_mreduce<<<512, 256>>>();
    k_p<<<dim3(8, 8, 2), 256>>>(W3);
    k_final_mma<<<dim3(2, 64), 256, SMEM_CORE>>>(b3, out);
}